// round 1
// baseline (speedup 1.0000x reference)
#include <cuda_runtime.h>
#include <cuda_bf16.h>
#include <math.h>

// ---------------------------------------------------------------------------
// GIN model:
//   x_in  = concat(x, t)                     [N,128]
//   agg   = scatter_add(x_in[src] -> dst)    [N,128]
//   h     = relu((x_in+agg) @ W1 + b1)       [N,256]
//   h     = relu(tanh(h @ W2 + b2))          [N,256]
//   p     = leaky(concat(h,x_in) @ P1 + pb1) [N,256]
//   p     = leaky(p @ P2 + pb2)              [N,256]
//   pred  = p @ P3 + pb3                     [N,1]
//   out   = [zeros(N), pred(N)]
// ---------------------------------------------------------------------------

#define MAXN 50000
#define INCH 128
#define HID  256

// scratch (static device arrays; allocation is forbidden)
__device__ float g_xin[(size_t)MAXN * INCH];
__device__ float g_agg[(size_t)MAXN * INCH];
__device__ float g_p[(size_t)MAXN * HID];
__device__ float g_q[(size_t)MAXN * HID];

// ---------------------------------------------------------------------------
// K0: build x_in = [x | t], zero agg
// ---------------------------------------------------------------------------
__global__ void build_xin_kernel(const float* __restrict__ x,
                                 const float* __restrict__ t,
                                 float* __restrict__ xin,
                                 float* __restrict__ agg,
                                 int M)
{
    int idx = blockIdx.x * blockDim.x + threadIdx.x;
    int total = M * INCH;
    if (idx >= total) return;
    int row = idx >> 7;       // /128
    int col = idx & 127;
    float v = (col < 127) ? x[(size_t)row * 127 + col] : t[row];
    xin[idx] = v;
    agg[idx] = 0.0f;
}

// ---------------------------------------------------------------------------
// K1: scatter add, one warp per edge, red.global.add.v4.f32
// ---------------------------------------------------------------------------
__device__ __forceinline__ void red_add_v4(float* addr, float4 v)
{
    asm volatile("red.global.add.v4.f32 [%0], {%1,%2,%3,%4};"
                 :: "l"(addr), "f"(v.x), "f"(v.y), "f"(v.z), "f"(v.w)
                 : "memory");
}

__global__ void scatter_kernel(const int* __restrict__ src,
                               const int* __restrict__ dst,
                               const float* __restrict__ xin,
                               float* __restrict__ agg,
                               int E)
{
    int warp = (blockIdx.x * blockDim.x + threadIdx.x) >> 5;
    int lane = threadIdx.x & 31;
    if (warp >= E) return;
    int s = src[warp];
    int d = dst[warp];
    const float4* ps = reinterpret_cast<const float4*>(xin + (size_t)s * INCH);
    float4 v = ps[lane];                       // 32 lanes * 16B = 512B = full row
    red_add_v4(agg + (size_t)d * INCH + lane * 4, v);
}

// ---------------------------------------------------------------------------
// GEMM: C[M,N] = act(A @ W + bias)
//   MODE 0: A          (stride K)
//   MODE 1: A + A2     (elementwise, both stride K)
//   MODE 2: concat: k < KA -> A (stride KA), else A2 (stride K-KA)
//   ACT: 0 none, 1 relu, 2 relu(tanh(.)), 3 leaky(0.2)
// 64x64x16 block tile, 4x4 per thread, 256 threads
// ---------------------------------------------------------------------------
template<int MODE, int ACT>
__global__ void gemm_kernel(const float* __restrict__ A,
                            const float* __restrict__ A2,
                            const float* __restrict__ W,
                            const float* __restrict__ bias,
                            float* __restrict__ C,
                            int M, int K, int N, int KA)
{
    constexpr int BM = 64, BN = 64, BK = 16;
    __shared__ float As[BK][BM];
    __shared__ float Bs[BK][BN];

    const int tid = threadIdx.x;       // 0..255
    const int tx = tid & 15;
    const int ty = tid >> 4;
    const int row0 = blockIdx.y * BM;
    const int col0 = blockIdx.x * BN;

    float acc[4][4];
    #pragma unroll
    for (int i = 0; i < 4; i++)
        #pragma unroll
        for (int j = 0; j < 4; j++)
            acc[i][j] = 0.0f;

    for (int k0 = 0; k0 < K; k0 += BK) {
        // A tile: 64 rows x 16 k
        #pragma unroll
        for (int i = 0; i < 4; i++) {
            int idx = tid + i * 256;
            int m  = idx >> 4;
            int kk = idx & 15;
            int row = row0 + m;
            int k   = k0 + kk;
            float v = 0.0f;
            if (row < M) {
                if (MODE == 0) {
                    v = A[(size_t)row * K + k];
                } else if (MODE == 1) {
                    v = A[(size_t)row * K + k] + A2[(size_t)row * K + k];
                } else {
                    if (k < KA) v = A[(size_t)row * KA + k];
                    else        v = A2[(size_t)row * (K - KA) + (k - KA)];
                }
            }
            As[kk][m] = v;
        }
        // B tile: 16 k x 64 cols (W is [K,N] row-major; K,N multiples of 16/64)
        #pragma unroll
        for (int i = 0; i < 4; i++) {
            int idx = tid + i * 256;
            int kk = idx >> 6;
            int n  = idx & 63;
            Bs[kk][n] = W[(size_t)(k0 + kk) * N + (col0 + n)];
        }
        __syncthreads();

        #pragma unroll
        for (int kk = 0; kk < BK; kk++) {
            float a[4], b[4];
            #pragma unroll
            for (int i = 0; i < 4; i++) a[i] = As[kk][ty * 4 + i];
            #pragma unroll
            for (int j = 0; j < 4; j++) b[j] = Bs[kk][tx * 4 + j];
            #pragma unroll
            for (int i = 0; i < 4; i++)
                #pragma unroll
                for (int j = 0; j < 4; j++)
                    acc[i][j] = fmaf(a[i], b[j], acc[i][j]);
        }
        __syncthreads();
    }

    #pragma unroll
    for (int i = 0; i < 4; i++) {
        int row = row0 + ty * 4 + i;
        if (row >= M) continue;
        #pragma unroll
        for (int j = 0; j < 4; j++) {
            int col = col0 + tx * 4 + j;
            float v = acc[i][j] + bias[col];
            if (ACT == 1)      v = fmaxf(v, 0.0f);
            else if (ACT == 2) { v = tanhf(v); v = fmaxf(v, 0.0f); }
            else if (ACT == 3) v = (v > 0.0f) ? v : 0.2f * v;
            C[(size_t)row * N + col] = v;
        }
    }
}

// ---------------------------------------------------------------------------
// K5: pred = p @ P3 + pb3 ; out[0..M)=0, out[M..2M)=pred. One warp per row.
// ---------------------------------------------------------------------------
__global__ void gemv_out_kernel(const float* __restrict__ Ain,
                                const float* __restrict__ P3,
                                const float* __restrict__ pb3,
                                float* __restrict__ out,
                                int M)
{
    int warp = (blockIdx.x * blockDim.x + threadIdx.x) >> 5;
    int lane = threadIdx.x & 31;
    if (warp >= M) return;
    const float4* a = reinterpret_cast<const float4*>(Ain + (size_t)warp * HID);
    const float4* w = reinterpret_cast<const float4*>(P3);
    float4 a0 = a[lane];
    float4 a1 = a[lane + 32];
    float4 w0 = __ldg(&w[lane]);
    float4 w1 = __ldg(&w[lane + 32]);
    float s = a0.x * w0.x + a0.y * w0.y + a0.z * w0.z + a0.w * w0.w
            + a1.x * w1.x + a1.y * w1.y + a1.z * w1.z + a1.w * w1.w;
    #pragma unroll
    for (int o = 16; o > 0; o >>= 1)
        s += __shfl_down_sync(0xffffffffu, s, o);
    if (lane == 0) {
        out[warp] = 0.0f;                       // t_pred = zeros
        out[(size_t)M + warp] = s + pb3[0];     // pred
    }
}

// ---------------------------------------------------------------------------
extern "C" void kernel_launch(void* const* d_in, const int* in_sizes, int n_in,
                              void* d_out, int out_size)
{
    const float* x   = (const float*)d_in[0];
    const float* t   = (const float*)d_in[1];
    // d_in[2] = z (unused by reference)
    const int*   ei  = (const int*)d_in[3];
    const float* W1  = (const float*)d_in[4];
    const float* b1  = (const float*)d_in[5];
    const float* W2  = (const float*)d_in[6];
    const float* b2  = (const float*)d_in[7];
    const float* P1  = (const float*)d_in[8];
    const float* pb1 = (const float*)d_in[9];
    const float* P2  = (const float*)d_in[10];
    const float* pb2 = (const float*)d_in[11];
    const float* P3  = (const float*)d_in[12];
    const float* pb3 = (const float*)d_in[13];
    float* out = (float*)d_out;

    const int M = in_sizes[1];          // N nodes (t has N elements)
    const int E = in_sizes[3] / 2;      // edge count

    float *xin, *agg, *p, *q;
    cudaGetSymbolAddress((void**)&xin, g_xin);
    cudaGetSymbolAddress((void**)&agg, g_agg);
    cudaGetSymbolAddress((void**)&p,   g_p);
    cudaGetSymbolAddress((void**)&q,   g_q);

    // K0: build x_in, zero agg
    {
        int total = M * INCH;
        build_xin_kernel<<<(total + 255) / 256, 256>>>(x, t, xin, agg, M);
    }
    // K1: scatter add (warp per edge)
    {
        int blocks = (E + 7) / 8;       // 8 warps / 256-thread block
        scatter_kernel<<<blocks, 256>>>(ei, ei + E, xin, agg, E);
    }

    dim3 grid(HID / 64, (M + 63) / 64);
    // L1: (x_in + agg) @ W1 + b1, relu        -> p
    gemm_kernel<1, 1><<<grid, 256>>>(xin, agg, W1, b1, p, M, INCH, HID, 0);
    // L2: p @ W2 + b2, relu(tanh)             -> q   (q = h)
    gemm_kernel<0, 2><<<grid, 256>>>(p, nullptr, W2, b2, q, M, HID, HID, 0);
    // L3: concat(h, x_in) @ P1 + pb1, leaky   -> p
    gemm_kernel<2, 3><<<grid, 256>>>(q, xin, P1, pb1, p, M, HID + INCH, HID, HID);
    // L4: p @ P2 + pb2, leaky                 -> q
    gemm_kernel<0, 3><<<grid, 256>>>(p, nullptr, P2, pb2, q, M, HID, HID, 0);
    // L5: q @ P3 + pb3 -> out[M..2M), out[0..M) = 0
    {
        int blocks = (M * 32 + 255) / 256;
        gemv_out_kernel<<<blocks, 256>>>(q, P3, pb3, out, M);
    }
}

// round 2
// speedup vs baseline: 1.4721x; 1.4721x over previous
#include <cuda_runtime.h>
#include <cuda_bf16.h>
#include <math.h>

#define MAXN 50000
#define INCH 128
#define HID  256

// scratch (static device arrays; allocation is forbidden)
__device__ float g_xin[(size_t)MAXN * INCH];
__device__ float g_agg[(size_t)MAXN * INCH];
__device__ float g_p[(size_t)MAXN * HID];
__device__ float g_q[(size_t)MAXN * HID];

// ---------------------------------------------------------------------------
// K0: build x_in = [x | t], zero agg
// ---------------------------------------------------------------------------
__global__ void build_xin_kernel(const float* __restrict__ x,
                                 const float* __restrict__ t,
                                 float* __restrict__ xin,
                                 float* __restrict__ agg,
                                 int M)
{
    int idx = blockIdx.x * blockDim.x + threadIdx.x;
    int total = M * INCH;
    if (idx >= total) return;
    int row = idx >> 7;
    int col = idx & 127;
    float v = (col < 127) ? x[(size_t)row * 127 + col] : t[row];
    xin[idx] = v;
    agg[idx] = 0.0f;
}

// ---------------------------------------------------------------------------
// K1: scatter add, one warp per edge, red.global.add.v4.f32
// ---------------------------------------------------------------------------
__device__ __forceinline__ void red_add_v4(float* addr, float4 v)
{
    asm volatile("red.global.add.v4.f32 [%0], {%1,%2,%3,%4};"
                 :: "l"(addr), "f"(v.x), "f"(v.y), "f"(v.z), "f"(v.w)
                 : "memory");
}

__global__ void scatter_kernel(const int* __restrict__ src,
                               const int* __restrict__ dst,
                               const float* __restrict__ xin,
                               float* __restrict__ agg,
                               int E)
{
    int warp = (blockIdx.x * blockDim.x + threadIdx.x) >> 5;
    int lane = threadIdx.x & 31;
    if (warp >= E) return;
    int s = src[warp];
    int d = dst[warp];
    const float4* ps = reinterpret_cast<const float4*>(xin + (size_t)s * INCH);
    float4 v = ps[lane];
    red_add_v4(agg + (size_t)d * INCH + lane * 4, v);
}

// ---------------------------------------------------------------------------
// GEMM: C[M,N] = act(A @ W + bias)
//   MODE 0: A            MODE 1: A + A2 (elementwise)
//   MODE 2: concat: k < KA -> A (stride KA), else A2 (stride K-KA)
//   ACT: 0 none, 1 relu, 2 relu(tanh), 3 leaky(0.2)
// 128x128x16 block tile, 8x8 per thread, 256 threads, reg-prefetch pipeline
// ---------------------------------------------------------------------------
template<int MODE>
__device__ __forceinline__ void load_a8(float4& v0, float4& v1,
                                        const float* __restrict__ A,
                                        const float* __restrict__ A2,
                                        int row, int k, int K, int KA, bool valid)
{
    if (!valid) {
        v0 = make_float4(0.f, 0.f, 0.f, 0.f);
        v1 = v0;
        return;
    }
    if (MODE == 0) {
        const float4* p = reinterpret_cast<const float4*>(A + (size_t)row * K + k);
        v0 = p[0]; v1 = p[1];
    } else if (MODE == 1) {
        const float4* p = reinterpret_cast<const float4*>(A  + (size_t)row * K + k);
        const float4* q = reinterpret_cast<const float4*>(A2 + (size_t)row * K + k);
        float4 a0 = p[0], a1 = p[1], c0 = q[0], c1 = q[1];
        v0 = make_float4(a0.x + c0.x, a0.y + c0.y, a0.z + c0.z, a0.w + c0.w);
        v1 = make_float4(a1.x + c1.x, a1.y + c1.y, a1.z + c1.z, a1.w + c1.w);
    } else {
        const float4* p;
        if (k < KA) p = reinterpret_cast<const float4*>(A  + (size_t)row * KA + k);
        else        p = reinterpret_cast<const float4*>(A2 + (size_t)row * (K - KA) + (k - KA));
        v0 = p[0]; v1 = p[1];
    }
}

template<int MODE, int ACT>
__global__ void __launch_bounds__(256, 2)
gemm_kernel(const float* __restrict__ A,
            const float* __restrict__ A2,
            const float* __restrict__ W,
            const float* __restrict__ bias,
            float* __restrict__ C,
            int M, int K, int N, int KA)
{
    constexpr int BM = 128, BN = 128, BK = 16;
    __shared__ float As[BK][BM + 4];
    __shared__ float Bs[BK][BN];

    const int tid = threadIdx.x;
    const int tx = tid & 15;          // 0..15 -> col frag
    const int ty = tid >> 4;          // 0..15 -> row frag
    const int row0 = blockIdx.y * BM;
    const int col0 = blockIdx.x * BN;

    // load mapping
    const int arow_l = tid >> 1;              // 0..127
    const int arow   = row0 + arow_l;
    const int ak     = (tid & 1) * 8;         // 0 or 8
    const bool avalid = (arow < M);
    const int bk_l   = tid >> 4;              // 0..15 (k within tile)
    const int bcol   = col0 + (tid & 15) * 8;

    float acc[8][8];
    #pragma unroll
    for (int i = 0; i < 8; i++)
        #pragma unroll
        for (int j = 0; j < 8; j++)
            acc[i][j] = 0.0f;

    // preload tile 0
    float4 pa0, pa1, pb0, pb1;
    load_a8<MODE>(pa0, pa1, A, A2, arow, ak, K, KA, avalid);
    {
        const float4* wp = reinterpret_cast<const float4*>(W + (size_t)bk_l * N + bcol);
        pb0 = wp[0]; pb1 = wp[1];
    }
    // store tile 0
    As[ak + 0][arow_l] = pa0.x; As[ak + 1][arow_l] = pa0.y;
    As[ak + 2][arow_l] = pa0.z; As[ak + 3][arow_l] = pa0.w;
    As[ak + 4][arow_l] = pa1.x; As[ak + 5][arow_l] = pa1.y;
    As[ak + 6][arow_l] = pa1.z; As[ak + 7][arow_l] = pa1.w;
    {
        float4* bp = reinterpret_cast<float4*>(&Bs[bk_l][(tid & 15) * 8]);
        bp[0] = pb0; bp[1] = pb1;
    }
    __syncthreads();

    for (int kt = 0; kt < K; kt += BK) {
        const bool more = (kt + BK) < K;
        if (more) {
            load_a8<MODE>(pa0, pa1, A, A2, arow, kt + BK + ak, K, KA, avalid);
            const float4* wp = reinterpret_cast<const float4*>(
                W + (size_t)(kt + BK + bk_l) * N + bcol);
            pb0 = wp[0]; pb1 = wp[1];
        }

        #pragma unroll
        for (int kk = 0; kk < BK; kk++) {
            float4 af0 = *reinterpret_cast<const float4*>(&As[kk][ty * 8]);
            float4 af1 = *reinterpret_cast<const float4*>(&As[kk][ty * 8 + 4]);
            float4 bf0 = *reinterpret_cast<const float4*>(&Bs[kk][tx * 8]);
            float4 bf1 = *reinterpret_cast<const float4*>(&Bs[kk][tx * 8 + 4]);
            float a[8] = {af0.x, af0.y, af0.z, af0.w, af1.x, af1.y, af1.z, af1.w};
            float b[8] = {bf0.x, bf0.y, bf0.z, bf0.w, bf1.x, bf1.y, bf1.z, bf1.w};
            #pragma unroll
            for (int i = 0; i < 8; i++)
                #pragma unroll
                for (int j = 0; j < 8; j++)
                    acc[i][j] = fmaf(a[i], b[j], acc[i][j]);
        }

        if (more) {
            __syncthreads();
            As[ak + 0][arow_l] = pa0.x; As[ak + 1][arow_l] = pa0.y;
            As[ak + 2][arow_l] = pa0.z; As[ak + 3][arow_l] = pa0.w;
            As[ak + 4][arow_l] = pa1.x; As[ak + 5][arow_l] = pa1.y;
            As[ak + 6][arow_l] = pa1.z; As[ak + 7][arow_l] = pa1.w;
            float4* bp = reinterpret_cast<float4*>(&Bs[bk_l][(tid & 15) * 8]);
            bp[0] = pb0; bp[1] = pb1;
            __syncthreads();
        }
    }

    // epilogue
    float bi[8];
    {
        const float4* bb = reinterpret_cast<const float4*>(bias + col0 + tx * 8);
        float4 b0 = bb[0], b1 = bb[1];
        bi[0] = b0.x; bi[1] = b0.y; bi[2] = b0.z; bi[3] = b0.w;
        bi[4] = b1.x; bi[5] = b1.y; bi[6] = b1.z; bi[7] = b1.w;
    }
    #pragma unroll
    for (int i = 0; i < 8; i++) {
        int row = row0 + ty * 8 + i;
        if (row >= M) continue;
        float v[8];
        #pragma unroll
        for (int j = 0; j < 8; j++) {
            float u = acc[i][j] + bi[j];
            if (ACT == 1)      u = fmaxf(u, 0.0f);
            else if (ACT == 2) { u = tanhf(u); u = fmaxf(u, 0.0f); }
            else if (ACT == 3) u = (u > 0.0f) ? u : 0.2f * u;
            v[j] = u;
        }
        float4* cp = reinterpret_cast<float4*>(C + (size_t)row * N + col0 + tx * 8);
        cp[0] = make_float4(v[0], v[1], v[2], v[3]);
        cp[1] = make_float4(v[4], v[5], v[6], v[7]);
    }
}

// ---------------------------------------------------------------------------
// K5: pred = p @ P3 + pb3 ; out[0..M)=0, out[M..2M)=pred. One warp per row.
// ---------------------------------------------------------------------------
__global__ void gemv_out_kernel(const float* __restrict__ Ain,
                                const float* __restrict__ P3,
                                const float* __restrict__ pb3,
                                float* __restrict__ out,
                                int M)
{
    int warp = (blockIdx.x * blockDim.x + threadIdx.x) >> 5;
    int lane = threadIdx.x & 31;
    if (warp >= M) return;
    const float4* a = reinterpret_cast<const float4*>(Ain + (size_t)warp * HID);
    const float4* w = reinterpret_cast<const float4*>(P3);
    float4 a0 = a[lane];
    float4 a1 = a[lane + 32];
    float4 w0 = __ldg(&w[lane]);
    float4 w1 = __ldg(&w[lane + 32]);
    float s = a0.x * w0.x + a0.y * w0.y + a0.z * w0.z + a0.w * w0.w
            + a1.x * w1.x + a1.y * w1.y + a1.z * w1.z + a1.w * w1.w;
    #pragma unroll
    for (int o = 16; o > 0; o >>= 1)
        s += __shfl_down_sync(0xffffffffu, s, o);
    if (lane == 0) {
        out[warp] = 0.0f;
        out[(size_t)M + warp] = s + pb3[0];
    }
}

// ---------------------------------------------------------------------------
extern "C" void kernel_launch(void* const* d_in, const int* in_sizes, int n_in,
                              void* d_out, int out_size)
{
    const float* x   = (const float*)d_in[0];
    const float* t   = (const float*)d_in[1];
    const int*   ei  = (const int*)d_in[3];
    const float* W1  = (const float*)d_in[4];
    const float* b1  = (const float*)d_in[5];
    const float* W2  = (const float*)d_in[6];
    const float* b2  = (const float*)d_in[7];
    const float* P1  = (const float*)d_in[8];
    const float* pb1 = (const float*)d_in[9];
    const float* P2  = (const float*)d_in[10];
    const float* pb2 = (const float*)d_in[11];
    const float* P3  = (const float*)d_in[12];
    const float* pb3 = (const float*)d_in[13];
    float* out = (float*)d_out;

    const int M = in_sizes[1];
    const int E = in_sizes[3] / 2;

    float *xin, *agg, *p, *q;
    cudaGetSymbolAddress((void**)&xin, g_xin);
    cudaGetSymbolAddress((void**)&agg, g_agg);
    cudaGetSymbolAddress((void**)&p,   g_p);
    cudaGetSymbolAddress((void**)&q,   g_q);

    {
        int total = M * INCH;
        build_xin_kernel<<<(total + 255) / 256, 256>>>(x, t, xin, agg, M);
    }
    {
        int blocks = (E + 7) / 8;
        scatter_kernel<<<blocks, 256>>>(ei, ei + E, xin, agg, E);
    }

    dim3 grid(HID / 128, (M + 127) / 128);
    gemm_kernel<1, 1><<<grid, 256>>>(xin, agg, W1, b1, p, M, INCH, HID, 0);
    gemm_kernel<0, 2><<<grid, 256>>>(p, nullptr, W2, b2, q, M, HID, HID, 0);
    gemm_kernel<2, 3><<<grid, 256>>>(q, xin, P1, pb1, p, M, HID + INCH, HID, HID);
    gemm_kernel<0, 3><<<grid, 256>>>(p, nullptr, P2, pb2, q, M, HID, HID, 0);
    {
        int blocks = (M * 32 + 255) / 256;
        gemv_out_kernel<<<blocks, 256>>>(q, P3, pb3, out, M);
    }
}

// round 4
// speedup vs baseline: 1.8582x; 1.2623x over previous
#include <cuda_runtime.h>
#include <cuda_bf16.h>
#include <math.h>
#include <cstdint>

#define MAXN 50000
#define INCH 128
#define HID  256

// tcgen05 is only available in the arch-specific (sm_103a / sm_100a) pass.
#if defined(__CUDA_ARCH__) && (defined(__CUDA_ARCH_FEAT_SM103_ALL) || defined(__CUDA_ARCH_FEAT_SM100_ALL))
#define HAS_TCGEN05 1
#else
#define HAS_TCGEN05 0
#endif

// ---------------------------------------------------------------------------
// PTX helpers (sm_103a tcgen05 / mbarrier) — only compiled under the feature
// ---------------------------------------------------------------------------
#if HAS_TCGEN05

__device__ __forceinline__ uint32_t smem_to_u32(const void* smem_ptr) {
    uint32_t addr;
    asm("{ .reg .u64 tmp; cvta.to.shared.u64 tmp, %1; cvt.u32.u64 %0, tmp; }"
        : "=r"(addr) : "l"(smem_ptr));
    return addr;
}

__device__ __forceinline__ uint32_t elect_one_pred() {
    uint32_t pred;
    asm volatile(
        "{\n\t"
        ".reg .pred p;\n\t"
        "elect.sync _|p, 0xFFFFFFFF;\n\t"
        "selp.b32 %0, 1, 0, p;\n\t"
        "}"
        : "=r"(pred));
    return pred;
}

#define TCGEN05_ALLOC(smem_result_addr, nCols) \
    asm volatile( \
        "tcgen05.alloc.cta_group::1.sync.aligned.shared::cta.b32 [%0], %1;" \
        :: "r"((uint32_t)(smem_result_addr)), "r"((uint32_t)(nCols)) \
        : "memory")

#define TCGEN05_DEALLOC(tmem_addr, nCols) \
    asm volatile( \
        "tcgen05.dealloc.cta_group::1.sync.aligned.b32 %0, %1;" \
        :: "r"(tmem_addr), "r"((uint32_t)(nCols)))

#define TCGEN05_RELINQUISH_ALLOC_PERMIT() \
    asm volatile("tcgen05.relinquish_alloc_permit.cta_group::1.sync.aligned;")

#define TCGEN05_COMMIT(mbar_smem_addr) \
    asm volatile( \
        "tcgen05.commit.cta_group::1.mbarrier::arrive::one.shared::cluster.b64 [%0];" \
        :: "r"((uint32_t)(mbar_smem_addr)) \
        : "memory")

#define TCGEN05_WAIT_LD() \
    asm volatile("tcgen05.wait::ld.sync.aligned;" ::: "memory")

#define TCGEN05_FENCE_BEFORE() \
    asm volatile("tcgen05.fence::before_thread_sync;" ::: "memory")

#define TCGEN05_FENCE_AFTER() \
    asm volatile("tcgen05.fence::after_thread_sync;" ::: "memory")

#define FENCE_PROXY_ASYNC_SHARED_CTA() \
    asm volatile("fence.proxy.async.shared::cta;" ::: "memory")

#define MBARRIER_INIT(mbar_smem_addr, count) \
    asm volatile( \
        "mbarrier.init.shared.b64 [%0], %1;" \
        :: "r"((uint32_t)(mbar_smem_addr)), "r"((uint32_t)(count)) \
        : "memory")

#define MBARRIER_WAIT_PARITY(mbar_smem_addr, phase_parity) do { \
    uint32_t _mbar = (uint32_t)(mbar_smem_addr); \
    uint32_t _parity = (uint32_t)(phase_parity); \
    uint32_t _done; \
    asm volatile( \
        "{\n\t" \
        ".reg .pred p;\n\t" \
        "mbarrier.try_wait.parity.acquire.cta.shared::cta.b64 p, [%1], %2;\n\t" \
        "selp.b32 %0, 1, 0, p;\n\t" \
        "}" \
        : "=r"(_done) : "r"(_mbar), "r"(_parity) : "memory"); \
    if (!_done) { \
        asm volatile( \
            "{\n\t" \
            ".reg .pred P1;\n\t" \
            "WAIT_LOOP_%=:\n\t" \
            "mbarrier.try_wait.parity.acquire.cta.shared::cta.b64 P1, [%0], %1, 0x989680;\n\t" \
            "@P1 bra.uni WAIT_DONE_%=;\n\t" \
            "bra.uni WAIT_LOOP_%=;\n\t" \
            "WAIT_DONE_%=:\n\t" \
            "}" \
            :: "r"(_mbar), "r"(_parity) : "memory"); \
    } \
} while(0)

#define TCGEN05_LD_32X32B_X32(r, tmem_addr) \
    asm volatile( \
        "tcgen05.ld.sync.aligned.32x32b.x32.b32 " \
        "{%0, %1, %2, %3, %4, %5, %6, %7, " \
        " %8, %9, %10, %11, %12, %13, %14, %15, " \
        " %16, %17, %18, %19, %20, %21, %22, %23, " \
        " %24, %25, %26, %27, %28, %29, %30, %31}, [%32];" \
        : "=r"((r)[0]),  "=r"((r)[1]),  "=r"((r)[2]),  "=r"((r)[3]), \
          "=r"((r)[4]),  "=r"((r)[5]),  "=r"((r)[6]),  "=r"((r)[7]), \
          "=r"((r)[8]),  "=r"((r)[9]),  "=r"((r)[10]), "=r"((r)[11]), \
          "=r"((r)[12]), "=r"((r)[13]), "=r"((r)[14]), "=r"((r)[15]), \
          "=r"((r)[16]), "=r"((r)[17]), "=r"((r)[18]), "=r"((r)[19]), \
          "=r"((r)[20]), "=r"((r)[21]), "=r"((r)[22]), "=r"((r)[23]), \
          "=r"((r)[24]), "=r"((r)[25]), "=r"((r)[26]), "=r"((r)[27]), \
          "=r"((r)[28]), "=r"((r)[29]), "=r"((r)[30]), "=r"((r)[31]) \
        : "r"(tmem_addr))

static constexpr uint64_t SMEM_DESC_BASE_SW128 =
    (uint64_t(2)  << 61)
    | (uint64_t(1) << 46)
    | (uint64_t(64) << 32)
    | (uint64_t(1) << 16);

#define MAKE_SMEM_DESC(base_addr) \
    (SMEM_DESC_BASE_SW128 | ((uint64_t)((base_addr) >> 4) & 0x3FFF))

// SS bf16 MMA, cta_group::1, fp32 accumulate
__device__ __forceinline__ void mma_f16_ss(uint32_t d, uint64_t a, uint64_t b,
                                           uint32_t idesc, uint32_t en)
{
    asm volatile(
        "{\n\t"
        ".reg .pred p;\n\t"
        "setp.ne.u32 p, %4, 0;\n\t"
        "tcgen05.mma.cta_group::1.kind::f16 [%0], %1, %2, %3, {%5, %5, %5, %5}, p;\n\t"
        "}"
        :: "r"(d), "l"(a), "l"(b), "r"(idesc), "r"(en), "r"(0u)
        : "memory");
}

#endif  // HAS_TCGEN05

// idesc: F32 acc, BF16 x BF16, M=128, N=256
static constexpr uint32_t IDESC =
    (1u << 4) | (1u << 7) | (1u << 10) | ((HID / 8) << 17) | ((128 / 16) << 24);

// ---------------------------------------------------------------------------
// scratch buffers
// ---------------------------------------------------------------------------
__device__ float g_xin[(size_t)MAXN * INCH];
__device__ float g_agg[(size_t)MAXN * INCH];
__device__ float g_q  [(size_t)MAXN * HID];
__device__ __nv_bfloat16 g_a1[(size_t)MAXN * 256];   // (xin+agg) split [hi|lo]
__device__ __nv_bfloat16 g_a2[(size_t)MAXN * 512];   // L1 out split
__device__ __nv_bfloat16 g_a3[(size_t)MAXN * 768];   // [h_hi|xin_hi|h_lo|xin_lo]
__device__ __nv_bfloat16 g_a4[(size_t)MAXN * 512];   // L3 out split
__device__ __nv_bfloat16 g_wt1[(size_t)HID * 384];
__device__ __nv_bfloat16 g_wt2[(size_t)HID * 768];
__device__ __nv_bfloat16 g_wt3[(size_t)HID * 1152];
__device__ __nv_bfloat16 g_wt4[(size_t)HID * 768];

__device__ __forceinline__ void split_bf16(float v, __nv_bfloat16& h, __nv_bfloat16& l)
{
    h = __float2bfloat16(v);
    l = __float2bfloat16(v - __bfloat162float(h));
}

__device__ __forceinline__ float apply_act(float v, int ACT)
{
    if (ACT == 1)      v = fmaxf(v, 0.f);
    else if (ACT == 2) v = fmaxf(tanhf(v), 0.f);
    else if (ACT == 3) v = (v > 0.f) ? v : 0.2f * v;
    return v;
}

// ---------------------------------------------------------------------------
// K0: build x_in (fp32 for scatter) + write xin split into A3 cols, zero agg
// ---------------------------------------------------------------------------
__global__ void build_xin_kernel(const float* __restrict__ x,
                                 const float* __restrict__ t,
                                 float* __restrict__ xin,
                                 float* __restrict__ agg,
                                 __nv_bfloat16* __restrict__ a3,
                                 int M)
{
    int idx = blockIdx.x * blockDim.x + threadIdx.x;
    int total = M * INCH;
    if (idx >= total) return;
    int row = idx >> 7;
    int col = idx & 127;
    float v = (col < 127) ? x[(size_t)row * 127 + col] : t[row];
    xin[idx] = v;
    agg[idx] = 0.0f;
    __nv_bfloat16 h, l;
    split_bf16(v, h, l);
    a3[(size_t)row * 768 + 256 + col] = h;
    a3[(size_t)row * 768 + 640 + col] = l;
}

// ---------------------------------------------------------------------------
// K1: scatter add, one warp per edge, red.global.add.v4.f32
// ---------------------------------------------------------------------------
__device__ __forceinline__ void red_add_v4(float* addr, float4 v)
{
    asm volatile("red.global.add.v4.f32 [%0], {%1,%2,%3,%4};"
                 :: "l"(addr), "f"(v.x), "f"(v.y), "f"(v.z), "f"(v.w)
                 : "memory");
}

__global__ void scatter_kernel(const int* __restrict__ src,
                               const int* __restrict__ dst,
                               const float* __restrict__ xin,
                               float* __restrict__ agg,
                               int E)
{
    int warp = (blockIdx.x * blockDim.x + threadIdx.x) >> 5;
    int lane = threadIdx.x & 31;
    if (warp >= E) return;
    int s = src[warp];
    int d = dst[warp];
    const float4* ps = reinterpret_cast<const float4*>(xin + (size_t)s * INCH);
    float4 v = ps[lane];
    red_add_v4(agg + (size_t)d * INCH + lane * 4, v);
}

// ---------------------------------------------------------------------------
// K2: split (xin + agg) into A1
// ---------------------------------------------------------------------------
__global__ void split1_kernel(const float* __restrict__ xin,
                              const float* __restrict__ agg,
                              __nv_bfloat16* __restrict__ a1,
                              int M)
{
    int idx = blockIdx.x * blockDim.x + threadIdx.x;
    int total = M * INCH;
    if (idx >= total) return;
    int row = idx >> 7;
    int col = idx & 127;
    float v = xin[idx] + agg[idx];
    __nv_bfloat16 h, l;
    split_bf16(v, h, l);
    a1[(size_t)row * 256 + col] = h;
    a1[(size_t)row * 256 + 128 + col] = l;
}

// ---------------------------------------------------------------------------
// K3: weight prep: Wt'[n][k'] (K-major, Ktot=3K):
//   k' in [0,K)   -> hi(W[k'][n])
//   k' in [K,2K)  -> lo(W[k'-K][n])
//   k' in [2K,3K) -> hi(W[k'-2K][n])
// ---------------------------------------------------------------------------
__global__ void prep_w_kernel(const float* __restrict__ W,
                              __nv_bfloat16* __restrict__ Wt,
                              int K)
{
    int idx = blockIdx.x * blockDim.x + threadIdx.x;
    int Ktot = 3 * K;
    int total = HID * Ktot;
    if (idx >= total) return;
    int n  = idx / Ktot;
    int kp = idx - n * Ktot;
    int seg = kp / K;
    int k   = kp - seg * K;
    float w = W[(size_t)k * HID + n];
    __nv_bfloat16 h, l;
    split_bf16(w, h, l);
    Wt[idx] = (seg == 1) ? l : h;
}

// ---------------------------------------------------------------------------
// tcgen05 GEMM: C[128-tile, 256] = act(A' @ W'^T + bias)
//   A: bf16 [M, strideA], hi cols [0,K), lo cols [K,2K);
//   k'-chunk reads src col (k' < K ? k' : k' - K)  (pairs hi/W_hi, hi/W_lo, lo/W_hi)
//   Wt: bf16 [256, Ktot] K-major
// Fallback (non-sm_103a pass): naive SIMT loop, correct but slow.
// ---------------------------------------------------------------------------
#define SMEM_BYTES 99328
#define SA_OFF(s) (1024u + (uint32_t)(s) * 49152u)
#define SB_OFF(s) (SA_OFF(s) + 16384u)

template<int ACT, bool SPLIT, bool F32OUT>
__global__ void __launch_bounds__(256)
tc_gemm(const __nv_bfloat16* __restrict__ A, int strideA, int K,
        const __nv_bfloat16* __restrict__ Wt, int Ktot,
        const float* __restrict__ bias,
        __nv_bfloat16* __restrict__ outHi, __nv_bfloat16* __restrict__ outLo,
        int strideO, float* __restrict__ outF, int M)
{
#if HAS_TCGEN05
    extern __shared__ char smem[];
    const uint32_t smem_base = smem_to_u32(smem);
    const int tid = threadIdx.x;
    const int wid = tid >> 5;
    const int row0 = blockIdx.x * 128;
    const int nch = Ktot / 64;

    if (wid == 0) {
        TCGEN05_ALLOC(smem_base, 256);
    }
    if (tid == 0) {
        MBARRIER_INIT(smem_base + 8, 1);
        MBARRIER_INIT(smem_base + 16, 1);
        MBARRIER_INIT(smem_base + 24, 1);
    }
    __syncthreads();
    uint32_t tmem_base;
    asm volatile("ld.shared.b32 %0, [%1];" : "=r"(tmem_base) : "r"(smem_base));

    int ph0 = 0, ph1 = 0;
    for (int c = 0; c < nch; c++) {
        const int s = c & 1;
        const uint32_t mb = smem_base + 8 + s * 8;
        if (c >= 2) {
            if (s == 0) { MBARRIER_WAIT_PARITY(mb, ph0); ph0 ^= 1; }
            else        { MBARRIER_WAIT_PARITY(mb, ph1); ph1 ^= 1; }
        }
        const uint32_t sa = SA_OFF(s);
        const uint32_t sb = SB_OFF(s);
        // --- A chunk: 128 rows x 64 bf16 (128B), SW128 swizzled
        {
            int k0 = c * 64;
            int sc = (k0 < K) ? k0 : (k0 - K);
            const __nv_bfloat16* Ab = A + sc;
            #pragma unroll
            for (int i = 0; i < 4; i++) {
                int id = tid + i * 256;
                int r = id >> 3, u = id & 7;
                uint4 v = make_uint4(0u, 0u, 0u, 0u);
                int row = row0 + r;
                if (row < M)
                    v = *reinterpret_cast<const uint4*>(Ab + (size_t)row * strideA + u * 8);
                int off = r * 128 + u * 16;
                off ^= (off >> 3) & 0x70;
                *reinterpret_cast<uint4*>(smem + sa + off) = v;
            }
        }
        // --- B chunk: 256 N-rows x 64 bf16 (128B), SW128 swizzled
        {
            const __nv_bfloat16* Bb = Wt + c * 64;
            #pragma unroll
            for (int i = 0; i < 8; i++) {
                int id = tid + i * 256;
                int n = id >> 3, u = id & 7;
                uint4 v = *reinterpret_cast<const uint4*>(Bb + (size_t)n * Ktot + u * 8);
                int off = n * 128 + u * 16;
                off ^= (off >> 3) & 0x70;
                *reinterpret_cast<uint4*>(smem + sb + off) = v;
            }
        }
        FENCE_PROXY_ASYNC_SHARED_CTA();
        __syncthreads();
        if (wid == 0) {
            if (elect_one_pred()) {
                uint64_t ad = MAKE_SMEM_DESC(smem_base + sa);
                uint64_t bd = MAKE_SMEM_DESC(smem_base + sb);
                #pragma unroll
                for (int st = 0; st < 4; st++)
                    mma_f16_ss(tmem_base, ad + st * 2, bd + st * 2, IDESC,
                               (c > 0 || st > 0) ? 1u : 0u);
                TCGEN05_COMMIT(mb);
            }
        }
    }
    if (wid == 0) {
        if (elect_one_pred()) TCGEN05_COMMIT(smem_base + 24);
    }

    // epilogue: warps 0-3 read D (128 x 256 fp32) from TMEM
    if (wid < 4) {
        MBARRIER_WAIT_PARITY(smem_base + 24, 0);
        TCGEN05_FENCE_AFTER();
        const int lane = tid & 31;
        const int row = row0 + wid * 32 + lane;
        const bool valid = (row < M);
        #pragma unroll 1
        for (int b = 0; b < 8; b++) {
            uint32_t regs[32];
            TCGEN05_LD_32X32B_X32(regs, tmem_base + b * 32);
            TCGEN05_WAIT_LD();
            if (valid) {
                #pragma unroll
                for (int j = 0; j < 32; j += 2) {
                    int col = b * 32 + j;
                    float v0 = apply_act(__uint_as_float(regs[j])     + __ldg(bias + col), ACT);
                    float v1 = apply_act(__uint_as_float(regs[j + 1]) + __ldg(bias + col + 1), ACT);
                    if (F32OUT) {
                        *reinterpret_cast<float2*>(outF + (size_t)row * HID + col)
                            = make_float2(v0, v1);
                    }
                    if (SPLIT) {
                        __nv_bfloat16 h0, l0, h1, l1;
                        split_bf16(v0, h0, l0);
                        split_bf16(v1, h1, l1);
                        __nv_bfloat162 hv; hv.x = h0; hv.y = h1;
                        __nv_bfloat162 lv; lv.x = l0; lv.y = l1;
                        *reinterpret_cast<__nv_bfloat162*>(outHi + (size_t)row * strideO + col) = hv;
                        *reinterpret_cast<__nv_bfloat162*>(outLo + (size_t)row * strideO + col) = lv;
                    }
                }
            }
        }
        TCGEN05_FENCE_BEFORE();
    }
    __syncthreads();
    if (wid == 0) {
        TCGEN05_RELINQUISH_ALLOC_PERMIT();
        TCGEN05_DEALLOC(tmem_base, 256);
    }
#else
    // ---- fallback (compiled only for non arch-specific targets): naive SIMT
    const int tid = threadIdx.x;
    const int row0 = blockIdx.x * 128;
    const int K2 = 2 * K;
    for (int idx = tid; idx < 128 * HID; idx += 256) {
        int r   = idx >> 8;        // / 256
        int col = idx & 255;
        int row = row0 + r;
        if (row >= M) continue;
        const __nv_bfloat16* Ar = A  + (size_t)row * strideA;
        const __nv_bfloat16* Wr = Wt + (size_t)col * Ktot;
        float sum = 0.0f;
        for (int kp = 0; kp < Ktot; kp++) {
            int sc = (kp < K) ? kp : (kp - K);   // [0,K)->hi, [K,2K)->hi, [2K,3K)->lo
            (void)K2;
            sum = fmaf(__bfloat162float(Ar[sc]), __bfloat162float(Wr[kp]), sum);
        }
        float v = apply_act(sum + bias[col], ACT);
        if (F32OUT) outF[(size_t)row * HID + col] = v;
        if (SPLIT) {
            __nv_bfloat16 h, l;
            split_bf16(v, h, l);
            outHi[(size_t)row * strideO + col] = h;
            outLo[(size_t)row * strideO + col] = l;
        }
    }
#endif
}

// ---------------------------------------------------------------------------
// K5: pred = p @ P3 + pb3 ; out[0..M)=0, out[M..2M)=pred. One warp per row.
// ---------------------------------------------------------------------------
__global__ void gemv_out_kernel(const float* __restrict__ Ain,
                                const float* __restrict__ P3,
                                const float* __restrict__ pb3,
                                float* __restrict__ out,
                                int M)
{
    int warp = (blockIdx.x * blockDim.x + threadIdx.x) >> 5;
    int lane = threadIdx.x & 31;
    if (warp >= M) return;
    const float4* a = reinterpret_cast<const float4*>(Ain + (size_t)warp * HID);
    const float4* w = reinterpret_cast<const float4*>(P3);
    float4 a0 = a[lane];
    float4 a1 = a[lane + 32];
    float4 w0 = __ldg(&w[lane]);
    float4 w1 = __ldg(&w[lane + 32]);
    float s = a0.x * w0.x + a0.y * w0.y + a0.z * w0.z + a0.w * w0.w
            + a1.x * w1.x + a1.y * w1.y + a1.z * w1.z + a1.w * w1.w;
    #pragma unroll
    for (int o = 16; o > 0; o >>= 1)
        s += __shfl_down_sync(0xffffffffu, s, o);
    if (lane == 0) {
        out[warp] = 0.0f;
        out[(size_t)M + warp] = s + pb3[0];
    }
}

// ---------------------------------------------------------------------------
extern "C" void kernel_launch(void* const* d_in, const int* in_sizes, int n_in,
                              void* d_out, int out_size)
{
    const float* x   = (const float*)d_in[0];
    const float* t   = (const float*)d_in[1];
    const int*   ei  = (const int*)d_in[3];
    const float* W1  = (const float*)d_in[4];
    const float* b1  = (const float*)d_in[5];
    const float* W2  = (const float*)d_in[6];
    const float* b2  = (const float*)d_in[7];
    const float* P1  = (const float*)d_in[8];
    const float* pb1 = (const float*)d_in[9];
    const float* P2  = (const float*)d_in[10];
    const float* pb2 = (const float*)d_in[11];
    const float* P3  = (const float*)d_in[12];
    const float* pb3 = (const float*)d_in[13];
    float* out = (float*)d_out;

    const int M = in_sizes[1];
    const int E = in_sizes[3] / 2;

    float *xin, *agg, *q;
    __nv_bfloat16 *a1, *a2, *a3, *a4, *wt1, *wt2, *wt3, *wt4;
    cudaGetSymbolAddress((void**)&xin, g_xin);
    cudaGetSymbolAddress((void**)&agg, g_agg);
    cudaGetSymbolAddress((void**)&q,   g_q);
    cudaGetSymbolAddress((void**)&a1,  g_a1);
    cudaGetSymbolAddress((void**)&a2,  g_a2);
    cudaGetSymbolAddress((void**)&a3,  g_a3);
    cudaGetSymbolAddress((void**)&a4,  g_a4);
    cudaGetSymbolAddress((void**)&wt1, g_wt1);
    cudaGetSymbolAddress((void**)&wt2, g_wt2);
    cudaGetSymbolAddress((void**)&wt3, g_wt3);
    cudaGetSymbolAddress((void**)&wt4, g_wt4);

    cudaFuncSetAttribute(tc_gemm<1, true,  false>,
                         cudaFuncAttributeMaxDynamicSharedMemorySize, SMEM_BYTES);
    cudaFuncSetAttribute(tc_gemm<2, true,  false>,
                         cudaFuncAttributeMaxDynamicSharedMemorySize, SMEM_BYTES);
    cudaFuncSetAttribute(tc_gemm<3, true,  false>,
                         cudaFuncAttributeMaxDynamicSharedMemorySize, SMEM_BYTES);
    cudaFuncSetAttribute(tc_gemm<3, false, true>,
                         cudaFuncAttributeMaxDynamicSharedMemorySize, SMEM_BYTES);

    // weight prep (tiny)
    prep_w_kernel<<<(HID * 384  + 255) / 256, 256>>>(W1, wt1, 128);
    prep_w_kernel<<<(HID * 768  + 255) / 256, 256>>>(W2, wt2, 256);
    prep_w_kernel<<<(HID * 1152 + 255) / 256, 256>>>(P1, wt3, 384);
    prep_w_kernel<<<(HID * 768  + 255) / 256, 256>>>(P2, wt4, 256);

    // graph feature path
    {
        int total = M * INCH;
        build_xin_kernel<<<(total + 255) / 256, 256>>>(x, t, xin, agg, a3, M);
    }
    {
        int blocks = (E + 7) / 8;
        scatter_kernel<<<blocks, 256>>>(ei, ei + E, xin, agg, E);
    }
    {
        int total = M * INCH;
        split1_kernel<<<(total + 255) / 256, 256>>>(xin, agg, a1, M);
    }

    const int tiles = (M + 127) / 128;
    // L1: relu((xin+agg) @ W1 + b1)       -> a2 split
    tc_gemm<1, true,  false><<<tiles, 256, SMEM_BYTES>>>(
        a1, 256, 128, wt1, 384, b1, a2, a2 + 256, 512, nullptr, M);
    // L2: relu(tanh(. @ W2 + b2))          -> a3 split (h part)
    tc_gemm<2, true,  false><<<tiles, 256, SMEM_BYTES>>>(
        a2, 512, 256, wt2, 768, b2, a3, a3 + 384, 768, nullptr, M);
    // L3: leaky(concat(h,xin) @ P1 + pb1)  -> a4 split
    tc_gemm<3, true,  false><<<tiles, 256, SMEM_BYTES>>>(
        a3, 768, 384, wt3, 1152, pb1, a4, a4 + 256, 512, nullptr, M);
    // L4: leaky(. @ P2 + pb2)              -> q fp32
    tc_gemm<3, false, true><<<tiles, 256, SMEM_BYTES>>>(
        a4, 512, 256, wt4, 768, pb2, nullptr, nullptr, 0, q, M);

    // L5: gemv + output
    {
        int blocks = (M * 32 + 255) / 256;
        gemv_out_kernel<<<blocks, 256>>>(q, P3, pb3, out, M);
    }
}

// round 5
// speedup vs baseline: 2.1197x; 1.1407x over previous
#include <cuda_runtime.h>
#include <cuda_bf16.h>
#include <math.h>
#include <cstdint>

#define MAXN 50000
#define INCH 128
#define HID  256

// tcgen05 is only available in the arch-specific (sm_103a / sm_100a) pass.
#if defined(__CUDA_ARCH__) && (defined(__CUDA_ARCH_FEAT_SM103_ALL) || defined(__CUDA_ARCH_FEAT_SM100_ALL))
#define HAS_TCGEN05 1
#else
#define HAS_TCGEN05 0
#endif

// ---------------------------------------------------------------------------
// PTX helpers
// ---------------------------------------------------------------------------
#if HAS_TCGEN05

__device__ __forceinline__ uint32_t smem_to_u32(const void* smem_ptr) {
    uint32_t addr;
    asm("{ .reg .u64 tmp; cvta.to.shared.u64 tmp, %1; cvt.u32.u64 %0, tmp; }"
        : "=r"(addr) : "l"(smem_ptr));
    return addr;
}

__device__ __forceinline__ uint32_t elect_one_pred() {
    uint32_t pred;
    asm volatile(
        "{\n\t"
        ".reg .pred p;\n\t"
        "elect.sync _|p, 0xFFFFFFFF;\n\t"
        "selp.b32 %0, 1, 0, p;\n\t"
        "}"
        : "=r"(pred));
    return pred;
}

#define TCGEN05_ALLOC(smem_result_addr, nCols) \
    asm volatile( \
        "tcgen05.alloc.cta_group::1.sync.aligned.shared::cta.b32 [%0], %1;" \
        :: "r"((uint32_t)(smem_result_addr)), "r"((uint32_t)(nCols)) \
        : "memory")

#define TCGEN05_DEALLOC(tmem_addr, nCols) \
    asm volatile( \
        "tcgen05.dealloc.cta_group::1.sync.aligned.b32 %0, %1;" \
        :: "r"(tmem_addr), "r"((uint32_t)(nCols)))

#define TCGEN05_RELINQUISH_ALLOC_PERMIT() \
    asm volatile("tcgen05.relinquish_alloc_permit.cta_group::1.sync.aligned;")

#define TCGEN05_COMMIT(mbar_smem_addr) \
    asm volatile( \
        "tcgen05.commit.cta_group::1.mbarrier::arrive::one.shared::cluster.b64 [%0];" \
        :: "r"((uint32_t)(mbar_smem_addr)) \
        : "memory")

#define TCGEN05_WAIT_LD() \
    asm volatile("tcgen05.wait::ld.sync.aligned;" ::: "memory")

#define TCGEN05_FENCE_BEFORE() \
    asm volatile("tcgen05.fence::before_thread_sync;" ::: "memory")

#define TCGEN05_FENCE_AFTER() \
    asm volatile("tcgen05.fence::after_thread_sync;" ::: "memory")

#define FENCE_PROXY_ASYNC_SHARED_CTA() \
    asm volatile("fence.proxy.async.shared::cta;" ::: "memory")

#define MBARRIER_INIT(mbar_smem_addr, count) \
    asm volatile( \
        "mbarrier.init.shared.b64 [%0], %1;" \
        :: "r"((uint32_t)(mbar_smem_addr)), "r"((uint32_t)(count)) \
        : "memory")

#define MBARRIER_WAIT_PARITY(mbar_smem_addr, phase_parity) do { \
    uint32_t _mbar = (uint32_t)(mbar_smem_addr); \
    uint32_t _parity = (uint32_t)(phase_parity); \
    uint32_t _done; \
    asm volatile( \
        "{\n\t" \
        ".reg .pred p;\n\t" \
        "mbarrier.try_wait.parity.acquire.cta.shared::cta.b64 p, [%1], %2;\n\t" \
        "selp.b32 %0, 1, 0, p;\n\t" \
        "}" \
        : "=r"(_done) : "r"(_mbar), "r"(_parity) : "memory"); \
    if (!_done) { \
        asm volatile( \
            "{\n\t" \
            ".reg .pred P1;\n\t" \
            "WAIT_LOOP_%=:\n\t" \
            "mbarrier.try_wait.parity.acquire.cta.shared::cta.b64 P1, [%0], %1, 0x989680;\n\t" \
            "@P1 bra.uni WAIT_DONE_%=;\n\t" \
            "bra.uni WAIT_LOOP_%=;\n\t" \
            "WAIT_DONE_%=:\n\t" \
            "}" \
            :: "r"(_mbar), "r"(_parity) : "memory"); \
    } \
} while(0)

#define TCGEN05_LD_32X32B_X32(r, tmem_addr) \
    asm volatile( \
        "tcgen05.ld.sync.aligned.32x32b.x32.b32 " \
        "{%0, %1, %2, %3, %4, %5, %6, %7, " \
        " %8, %9, %10, %11, %12, %13, %14, %15, " \
        " %16, %17, %18, %19, %20, %21, %22, %23, " \
        " %24, %25, %26, %27, %28, %29, %30, %31}, [%32];" \
        : "=r"((r)[0]),  "=r"((r)[1]),  "=r"((r)[2]),  "=r"((r)[3]), \
          "=r"((r)[4]),  "=r"((r)[5]),  "=r"((r)[6]),  "=r"((r)[7]), \
          "=r"((r)[8]),  "=r"((r)[9]),  "=r"((r)[10]), "=r"((r)[11]), \
          "=r"((r)[12]), "=r"((r)[13]), "=r"((r)[14]), "=r"((r)[15]), \
          "=r"((r)[16]), "=r"((r)[17]), "=r"((r)[18]), "=r"((r)[19]), \
          "=r"((r)[20]), "=r"((r)[21]), "=r"((r)[22]), "=r"((r)[23]), \
          "=r"((r)[24]), "=r"((r)[25]), "=r"((r)[26]), "=r"((r)[27]), \
          "=r"((r)[28]), "=r"((r)[29]), "=r"((r)[30]), "=r"((r)[31]) \
        : "r"(tmem_addr))

static constexpr uint64_t SMEM_DESC_BASE_SW128 =
    (uint64_t(2)  << 61)
    | (uint64_t(1) << 46)
    | (uint64_t(64) << 32)
    | (uint64_t(1) << 16);

#define MAKE_SMEM_DESC(base_addr) \
    (SMEM_DESC_BASE_SW128 | ((uint64_t)((base_addr) >> 4) & 0x3FFF))

// SS bf16 MMA, cta_group::1, fp32 accumulate
__device__ __forceinline__ void mma_f16_ss(uint32_t d, uint64_t a, uint64_t b,
                                           uint32_t idesc, uint32_t en)
{
    asm volatile(
        "{\n\t"
        ".reg .pred p;\n\t"
        "setp.ne.u32 p, %4, 0;\n\t"
        "tcgen05.mma.cta_group::1.kind::f16 [%0], %1, %2, %3, {%5, %5, %5, %5}, p;\n\t"
        "}"
        :: "r"(d), "l"(a), "l"(b), "r"(idesc), "r"(en), "r"(0u)
        : "memory");
}

#endif  // HAS_TCGEN05

// idesc: F32 acc, BF16 x BF16, M=128, N=256
static constexpr uint32_t IDESC =
    (1u << 4) | (1u << 7) | (1u << 10) | ((HID / 8) << 17) | ((128 / 16) << 24);

// ---------------------------------------------------------------------------
// scratch buffers
// ---------------------------------------------------------------------------
__device__ float g_xin[(size_t)MAXN * INCH];
__device__ float g_agg[(size_t)MAXN * INCH];
__device__ __nv_bfloat16 g_a2[(size_t)MAXN * 512];   // L1 out split [hi|lo]
__device__ __nv_bfloat16 g_a3[(size_t)MAXN * 768];   // [h_hi|xin_hi|h_lo|xin_lo]
__device__ __nv_bfloat16 g_a4[(size_t)MAXN * 512];   // L3 out split [hi|lo]
__device__ __nv_bfloat16 g_wt1[(size_t)HID * 384];
__device__ __nv_bfloat16 g_wt2[(size_t)HID * 768];
__device__ __nv_bfloat16 g_wt3[(size_t)HID * 1152];
__device__ __nv_bfloat16 g_wt4[(size_t)HID * 768];

__device__ __forceinline__ void split_bf16(float v, __nv_bfloat16& h, __nv_bfloat16& l)
{
    h = __float2bfloat16(v);
    l = __float2bfloat16(v - __bfloat162float(h));
}

__device__ __forceinline__ float apply_act(float v, int ACT)
{
    if (ACT == 1)      v = fmaxf(v, 0.f);
    else if (ACT == 2) v = fmaxf(tanhf(v), 0.f);
    else if (ACT == 3) v = (v > 0.f) ? v : 0.2f * v;
    return v;
}

// ---------------------------------------------------------------------------
// K0: build x_in (fp32 for scatter) + write xin split into A3 cols, zero agg
// ---------------------------------------------------------------------------
__global__ void build_xin_kernel(const float* __restrict__ x,
                                 const float* __restrict__ t,
                                 float* __restrict__ xin,
                                 float* __restrict__ agg,
                                 __nv_bfloat16* __restrict__ a3,
                                 int M)
{
    int idx = blockIdx.x * blockDim.x + threadIdx.x;
    int total = M * INCH;
    if (idx >= total) return;
    int row = idx >> 7;
    int col = idx & 127;
    float v = (col < 127) ? x[(size_t)row * 127 + col] : t[row];
    xin[idx] = v;
    agg[idx] = 0.0f;
    __nv_bfloat16 h, l;
    split_bf16(v, h, l);
    a3[(size_t)row * 768 + 256 + col] = h;
    a3[(size_t)row * 768 + 640 + col] = l;
}

// ---------------------------------------------------------------------------
// K1: scatter add, one warp per edge, red.global.add.v4.f32
// ---------------------------------------------------------------------------
__device__ __forceinline__ void red_add_v4(float* addr, float4 v)
{
    asm volatile("red.global.add.v4.f32 [%0], {%1,%2,%3,%4};"
                 :: "l"(addr), "f"(v.x), "f"(v.y), "f"(v.z), "f"(v.w)
                 : "memory");
}

__global__ void scatter_kernel(const int* __restrict__ src,
                               const int* __restrict__ dst,
                               const float* __restrict__ xin,
                               float* __restrict__ agg,
                               int E)
{
    int warp = (blockIdx.x * blockDim.x + threadIdx.x) >> 5;
    int lane = threadIdx.x & 31;
    if (warp >= E) return;
    int s = src[warp];
    int d = dst[warp];
    const float4* ps = reinterpret_cast<const float4*>(xin + (size_t)s * INCH);
    float4 v = ps[lane];
    red_add_v4(agg + (size_t)d * INCH + lane * 4, v);
}

// ---------------------------------------------------------------------------
// K2: all weight preps in one kernel.
// Wt'[n][k'] (K-major, Ktot=3K): seg0 -> hi, seg1 -> lo, seg2 -> hi
// ---------------------------------------------------------------------------
__device__ __forceinline__ void prep_one(const float* __restrict__ W,
                                         __nv_bfloat16* __restrict__ Wt,
                                         int K, int idx)
{
    int Ktot = 3 * K;
    int n  = idx / Ktot;
    int kp = idx - n * Ktot;
    int seg = kp / K;
    int k   = kp - seg * K;
    float w = W[(size_t)k * HID + n];
    __nv_bfloat16 h, l;
    split_bf16(w, h, l);
    Wt[idx] = (seg == 1) ? l : h;
}

__global__ void prep_all_kernel(const float* __restrict__ W1,
                                const float* __restrict__ W2,
                                const float* __restrict__ P1,
                                const float* __restrict__ P2,
                                __nv_bfloat16* __restrict__ wt1,
                                __nv_bfloat16* __restrict__ wt2,
                                __nv_bfloat16* __restrict__ wt3,
                                __nv_bfloat16* __restrict__ wt4)
{
    const int s1 = HID * 384;
    const int s2 = s1 + HID * 768;
    const int s3 = s2 + HID * 1152;
    const int s4 = s3 + HID * 768;
    int idx = blockIdx.x * blockDim.x + threadIdx.x;
    if (idx < s1)       prep_one(W1, wt1, 128, idx);
    else if (idx < s2)  prep_one(W2, wt2, 256, idx - s1);
    else if (idx < s3)  prep_one(P1, wt3, 384, idx - s2);
    else if (idx < s4)  prep_one(P2, wt4, 256, idx - s3);
}

// ---------------------------------------------------------------------------
// tcgen05 GEMM: C[128-tile, 256] = act(A' @ W'^T + bias)
//   AMODE 0: A bf16 [M, strideA], hi cols [0,K), lo cols [K,2K)
//   AMODE 1: A built on-the-fly from fp32 xin+agg (K=128): hi/lo split inline
//   chunk k0 reads A-col (k0 < K ? k0 : k0 - K)
//   Wt: bf16 [256, Ktot] K-major ([hi|lo|hi])
//   SPLIT:  write bf16 hi/lo activations (stride strideO)
//   GEMV:   fuse final 256->1 layer: out[row]=0, out[M+row]=dot(v,P3)+pb3
// ---------------------------------------------------------------------------
#define SMEM_BYTES 99328
#define SA_OFF(s) (1024u + (uint32_t)(s) * 49152u)
#define SB_OFF(s) (SA_OFF(s) + 16384u)

template<int AMODE, int ACT, bool SPLIT, bool GEMV>
__global__ void __launch_bounds__(256)
tc_gemm(const __nv_bfloat16* __restrict__ A,
        const float* __restrict__ Axin, const float* __restrict__ Aagg,
        int strideA, int K,
        const __nv_bfloat16* __restrict__ Wt, int Ktot,
        const float* __restrict__ bias,
        __nv_bfloat16* __restrict__ outHi, __nv_bfloat16* __restrict__ outLo,
        int strideO,
        float* __restrict__ outF, const float* __restrict__ P3,
        const float* __restrict__ pb3, int M)
{
#if HAS_TCGEN05
    extern __shared__ char smem[];
    const uint32_t smem_base = smem_to_u32(smem);
    const int tid = threadIdx.x;
    const int wid = tid >> 5;
    const int row0 = blockIdx.x * 128;
    const int nch = Ktot / 64;

    if (wid == 0) {
        TCGEN05_ALLOC(smem_base, 256);
    }
    if (tid == 0) {
        MBARRIER_INIT(smem_base + 8, 1);
        MBARRIER_INIT(smem_base + 16, 1);
        MBARRIER_INIT(smem_base + 24, 1);
    }
    __syncthreads();
    uint32_t tmem_base;
    asm volatile("ld.shared.b32 %0, [%1];" : "=r"(tmem_base) : "r"(smem_base));

    int ph0 = 0, ph1 = 0;
    for (int c = 0; c < nch; c++) {
        const int s = c & 1;
        const uint32_t mb = smem_base + 8 + s * 8;
        if (c >= 2) {
            if (s == 0) { MBARRIER_WAIT_PARITY(mb, ph0); ph0 ^= 1; }
            else        { MBARRIER_WAIT_PARITY(mb, ph1); ph1 ^= 1; }
        }
        const uint32_t sa = SA_OFF(s);
        const uint32_t sb = SB_OFF(s);
        // --- A chunk: 128 rows x 64 bf16 (128B), SW128 swizzled
        {
            int k0 = c * 64;
            int sc = (k0 < K) ? k0 : (k0 - K);
            #pragma unroll
            for (int i = 0; i < 4; i++) {
                int id = tid + i * 256;
                int r = id >> 3, u = id & 7;
                uint4 v = make_uint4(0u, 0u, 0u, 0u);
                int row = row0 + r;
                if (row < M) {
                    if (AMODE == 0) {
                        v = *reinterpret_cast<const uint4*>(
                            A + (size_t)row * strideA + sc + u * 8);
                    } else {
                        // fp32 fused split: A-col space [0,128)=hi, [128,256)=lo
                        int col = sc + u * 8;
                        bool hi = (col < 128);
                        int fcol = hi ? col : (col - 128);
                        const float4* xp = reinterpret_cast<const float4*>(
                            Axin + (size_t)row * 128 + fcol);
                        const float4* gp = reinterpret_cast<const float4*>(
                            Aagg + (size_t)row * 128 + fcol);
                        float4 x0 = xp[0], x1 = xp[1], g0 = gp[0], g1 = gp[1];
                        float f[8] = {x0.x + g0.x, x0.y + g0.y, x0.z + g0.z, x0.w + g0.w,
                                      x1.x + g1.x, x1.y + g1.y, x1.z + g1.z, x1.w + g1.w};
                        __nv_bfloat16 o[8];
                        #pragma unroll
                        for (int j = 0; j < 8; j++) {
                            __nv_bfloat16 h, l;
                            split_bf16(f[j], h, l);
                            o[j] = hi ? h : l;
                        }
                        v = *reinterpret_cast<uint4*>(o);
                    }
                }
                int off = r * 128 + u * 16;
                off ^= (off >> 3) & 0x70;
                *reinterpret_cast<uint4*>(smem + sa + off) = v;
            }
        }
        // --- B chunk: 256 N-rows x 64 bf16 (128B), SW128 swizzled
        {
            const __nv_bfloat16* Bb = Wt + c * 64;
            #pragma unroll
            for (int i = 0; i < 8; i++) {
                int id = tid + i * 256;
                int n = id >> 3, u = id & 7;
                uint4 v = *reinterpret_cast<const uint4*>(Bb + (size_t)n * Ktot + u * 8);
                int off = n * 128 + u * 16;
                off ^= (off >> 3) & 0x70;
                *reinterpret_cast<uint4*>(smem + sb + off) = v;
            }
        }
        FENCE_PROXY_ASYNC_SHARED_CTA();
        __syncthreads();
        if (wid == 0) {
            if (elect_one_pred()) {
                uint64_t ad = MAKE_SMEM_DESC(smem_base + sa);
                uint64_t bd = MAKE_SMEM_DESC(smem_base + sb);
                #pragma unroll
                for (int st = 0; st < 4; st++)
                    mma_f16_ss(tmem_base, ad + st * 2, bd + st * 2, IDESC,
                               (c > 0 || st > 0) ? 1u : 0u);
                TCGEN05_COMMIT(mb);
            }
        }
    }
    if (wid == 0) {
        if (elect_one_pred()) TCGEN05_COMMIT(smem_base + 24);
    }

    // epilogue: warps 0-3 read D (128 x 256 fp32) from TMEM, 64 cols per batch
    if (wid < 4) {
        MBARRIER_WAIT_PARITY(smem_base + 24, 0);
        TCGEN05_FENCE_AFTER();
        const int lane = tid & 31;
        const int row = row0 + wid * 32 + lane;
        const bool valid = (row < M);
        float gsum = 0.0f;
        #pragma unroll 1
        for (int b = 0; b < 4; b++) {
            uint32_t regs[64];
            TCGEN05_LD_32X32B_X32(regs, tmem_base + b * 64);
            TCGEN05_LD_32X32B_X32(regs + 32, tmem_base + b * 64 + 32);
            TCGEN05_WAIT_LD();
            if (valid) {
                #pragma unroll
                for (int j = 0; j < 64; j += 2) {
                    int col = b * 64 + j;
                    float v0 = apply_act(__uint_as_float(regs[j])     + __ldg(bias + col), ACT);
                    float v1 = apply_act(__uint_as_float(regs[j + 1]) + __ldg(bias + col + 1), ACT);
                    if (GEMV) {
                        gsum += v0 * __ldg(P3 + col) + v1 * __ldg(P3 + col + 1);
                    }
                    if (SPLIT) {
                        __nv_bfloat16 h0, l0, h1, l1;
                        split_bf16(v0, h0, l0);
                        split_bf16(v1, h1, l1);
                        __nv_bfloat162 hv; hv.x = h0; hv.y = h1;
                        __nv_bfloat162 lv; lv.x = l0; lv.y = l1;
                        *reinterpret_cast<__nv_bfloat162*>(outHi + (size_t)row * strideO + col) = hv;
                        *reinterpret_cast<__nv_bfloat162*>(outLo + (size_t)row * strideO + col) = lv;
                    }
                }
            }
        }
        if (GEMV && valid) {
            outF[row] = 0.0f;                       // t_pred
            outF[(size_t)M + row] = gsum + __ldg(pb3);
        }
        TCGEN05_FENCE_BEFORE();
    }
    __syncthreads();
    if (wid == 0) {
        TCGEN05_RELINQUISH_ALLOC_PERMIT();
        TCGEN05_DEALLOC(tmem_base, 256);
    }
#else
    // ---- fallback (non arch-specific pass only): correct, slow SIMT path
    const int tid = threadIdx.x;
    const int row0 = blockIdx.x * 128;
    if (GEMV) {
        if (tid < 128) {
            int row = row0 + tid;
            if (row < M) {
                float gsum = 0.0f;
                for (int col = 0; col < HID; col++) {
                    const __nv_bfloat16* Wr = Wt + (size_t)col * Ktot;
                    float sum = 0.0f;
                    for (int kp = 0; kp < Ktot; kp++) {
                        int sc = (kp < K) ? kp : (kp - K);
                        float av;
                        if (AMODE == 0) {
                            av = __bfloat162float(A[(size_t)row * strideA + sc]);
                        } else {
                            bool hi = (sc < 128);
                            int fc = hi ? sc : sc - 128;
                            float f = Axin[(size_t)row * 128 + fc] + Aagg[(size_t)row * 128 + fc];
                            __nv_bfloat16 h, l; split_bf16(f, h, l);
                            av = __bfloat162float(hi ? h : l);
                        }
                        sum = fmaf(av, __bfloat162float(Wr[kp]), sum);
                    }
                    float v = apply_act(sum + bias[col], ACT);
                    gsum += v * P3[col];
                }
                outF[row] = 0.0f;
                outF[(size_t)M + row] = gsum + pb3[0];
            }
        }
    } else {
        for (int idx = tid; idx < 128 * HID; idx += 256) {
            int r = idx >> 8;
            int col = idx & 255;
            int row = row0 + r;
            if (row >= M) continue;
            const __nv_bfloat16* Wr = Wt + (size_t)col * Ktot;
            float sum = 0.0f;
            for (int kp = 0; kp < Ktot; kp++) {
                int sc = (kp < K) ? kp : (kp - K);
                float av;
                if (AMODE == 0) {
                    av = __bfloat162float(A[(size_t)row * strideA + sc]);
                } else {
                    bool hi = (sc < 128);
                    int fc = hi ? sc : sc - 128;
                    float f = Axin[(size_t)row * 128 + fc] + Aagg[(size_t)row * 128 + fc];
                    __nv_bfloat16 h, l; split_bf16(f, h, l);
                    av = __bfloat162float(hi ? h : l);
                }
                sum = fmaf(av, __bfloat162float(Wr[kp]), sum);
            }
            float v = apply_act(sum + bias[col], ACT);
            if (SPLIT) {
                __nv_bfloat16 h, l;
                split_bf16(v, h, l);
                outHi[(size_t)row * strideO + col] = h;
                outLo[(size_t)row * strideO + col] = l;
            }
        }
    }
#endif
}

// ---------------------------------------------------------------------------
extern "C" void kernel_launch(void* const* d_in, const int* in_sizes, int n_in,
                              void* d_out, int out_size)
{
    const float* x   = (const float*)d_in[0];
    const float* t   = (const float*)d_in[1];
    const int*   ei  = (const int*)d_in[3];
    const float* W1  = (const float*)d_in[4];
    const float* b1  = (const float*)d_in[5];
    const float* W2  = (const float*)d_in[6];
    const float* b2  = (const float*)d_in[7];
    const float* P1  = (const float*)d_in[8];
    const float* pb1 = (const float*)d_in[9];
    const float* P2  = (const float*)d_in[10];
    const float* pb2 = (const float*)d_in[11];
    const float* P3  = (const float*)d_in[12];
    const float* pb3 = (const float*)d_in[13];
    float* out = (float*)d_out;

    const int M = in_sizes[1];
    const int E = in_sizes[3] / 2;

    float *xin, *agg;
    __nv_bfloat16 *a2, *a3, *a4, *wt1, *wt2, *wt3, *wt4;
    cudaGetSymbolAddress((void**)&xin, g_xin);
    cudaGetSymbolAddress((void**)&agg, g_agg);
    cudaGetSymbolAddress((void**)&a2,  g_a2);
    cudaGetSymbolAddress((void**)&a3,  g_a3);
    cudaGetSymbolAddress((void**)&a4,  g_a4);
    cudaGetSymbolAddress((void**)&wt1, g_wt1);
    cudaGetSymbolAddress((void**)&wt2, g_wt2);
    cudaGetSymbolAddress((void**)&wt3, g_wt3);
    cudaGetSymbolAddress((void**)&wt4, g_wt4);

    cudaFuncSetAttribute(tc_gemm<1, 1, true,  false>,
                         cudaFuncAttributeMaxDynamicSharedMemorySize, SMEM_BYTES);
    cudaFuncSetAttribute(tc_gemm<0, 2, true,  false>,
                         cudaFuncAttributeMaxDynamicSharedMemorySize, SMEM_BYTES);
    cudaFuncSetAttribute(tc_gemm<0, 3, true,  false>,
                         cudaFuncAttributeMaxDynamicSharedMemorySize, SMEM_BYTES);
    cudaFuncSetAttribute(tc_gemm<0, 3, false, true>,
                         cudaFuncAttributeMaxDynamicSharedMemorySize, SMEM_BYTES);

    // 1: build x_in, zero agg, write xin split into a3
    {
        int total = M * INCH;
        build_xin_kernel<<<(total + 255) / 256, 256>>>(x, t, xin, agg, a3, M);
    }
    // 2: scatter add
    {
        int blocks = (E + 7) / 8;
        scatter_kernel<<<blocks, 256>>>(ei, ei + E, xin, agg, E);
    }
    // 3: weight prep (all four)
    {
        int total = HID * (384 + 768 + 1152 + 768);
        prep_all_kernel<<<(total + 255) / 256, 256>>>(W1, W2, P1, P2,
                                                      wt1, wt2, wt3, wt4);
    }

    const int tiles = (M + 127) / 128;
    // 4: L1 relu((xin+agg) @ W1 + b1)  [A split fused]   -> a2
    tc_gemm<1, 1, true,  false><<<tiles, 256, SMEM_BYTES>>>(
        nullptr, xin, agg, 0, 128, wt1, 384, b1,
        a2, a2 + 256, 512, nullptr, nullptr, nullptr, M);
    // 5: L2 relu(tanh(. @ W2 + b2))                       -> a3 (h part)
    tc_gemm<0, 2, true,  false><<<tiles, 256, SMEM_BYTES>>>(
        a2, nullptr, nullptr, 512, 256, wt2, 768, b2,
        a3, a3 + 384, 768, nullptr, nullptr, nullptr, M);
    // 6: L3 leaky(concat(h,xin) @ P1 + pb1)               -> a4
    tc_gemm<0, 3, true,  false><<<tiles, 256, SMEM_BYTES>>>(
        a3, nullptr, nullptr, 768, 384, wt3, 1152, pb1,
        a4, a4 + 256, 512, nullptr, nullptr, nullptr, M);
    // 7: L4 leaky(. @ P2 + pb2) fused with P3 gemv + out
    tc_gemm<0, 3, false, true><<<tiles, 256, SMEM_BYTES>>>(
        a4, nullptr, nullptr, 512, 256, wt4, 768, pb2,
        nullptr, nullptr, 0, out, P3, pb3, M);
}

// round 6
// speedup vs baseline: 2.1507x; 1.0146x over previous
#include <cuda_runtime.h>
#include <cuda_bf16.h>
#include <math.h>
#include <cstdint>

#define MAXN 50000
#define INCH 128
#define HID  256

// tcgen05 is only available in the arch-specific (sm_103a / sm_100a) pass.
#if defined(__CUDA_ARCH__) && (defined(__CUDA_ARCH_FEAT_SM103_ALL) || defined(__CUDA_ARCH_FEAT_SM100_ALL))
#define HAS_TCGEN05 1
#else
#define HAS_TCGEN05 0
#endif

// ---------------------------------------------------------------------------
// PTX helpers
// ---------------------------------------------------------------------------
#if HAS_TCGEN05

__device__ __forceinline__ uint32_t smem_to_u32(const void* smem_ptr) {
    uint32_t addr;
    asm("{ .reg .u64 tmp; cvta.to.shared.u64 tmp, %1; cvt.u32.u64 %0, tmp; }"
        : "=r"(addr) : "l"(smem_ptr));
    return addr;
}

__device__ __forceinline__ uint32_t elect_one_pred() {
    uint32_t pred;
    asm volatile(
        "{\n\t"
        ".reg .pred p;\n\t"
        "elect.sync _|p, 0xFFFFFFFF;\n\t"
        "selp.b32 %0, 1, 0, p;\n\t"
        "}"
        : "=r"(pred));
    return pred;
}

#define TCGEN05_ALLOC(smem_result_addr, nCols) \
    asm volatile( \
        "tcgen05.alloc.cta_group::1.sync.aligned.shared::cta.b32 [%0], %1;" \
        :: "r"((uint32_t)(smem_result_addr)), "r"((uint32_t)(nCols)) \
        : "memory")

#define TCGEN05_DEALLOC(tmem_addr, nCols) \
    asm volatile( \
        "tcgen05.dealloc.cta_group::1.sync.aligned.b32 %0, %1;" \
        :: "r"(tmem_addr), "r"((uint32_t)(nCols)))

#define TCGEN05_RELINQUISH_ALLOC_PERMIT() \
    asm volatile("tcgen05.relinquish_alloc_permit.cta_group::1.sync.aligned;")

#define TCGEN05_COMMIT(mbar_smem_addr) \
    asm volatile( \
        "tcgen05.commit.cta_group::1.mbarrier::arrive::one.shared::cluster.b64 [%0];" \
        :: "r"((uint32_t)(mbar_smem_addr)) \
        : "memory")

#define TCGEN05_WAIT_LD() \
    asm volatile("tcgen05.wait::ld.sync.aligned;" ::: "memory")

#define TCGEN05_FENCE_BEFORE() \
    asm volatile("tcgen05.fence::before_thread_sync;" ::: "memory")

#define TCGEN05_FENCE_AFTER() \
    asm volatile("tcgen05.fence::after_thread_sync;" ::: "memory")

#define FENCE_PROXY_ASYNC_SHARED_CTA() \
    asm volatile("fence.proxy.async.shared::cta;" ::: "memory")

#define MBARRIER_INIT(mbar_smem_addr, count) \
    asm volatile( \
        "mbarrier.init.shared.b64 [%0], %1;" \
        :: "r"((uint32_t)(mbar_smem_addr)), "r"((uint32_t)(count)) \
        : "memory")

#define MBARRIER_WAIT_PARITY(mbar_smem_addr, phase_parity) do { \
    uint32_t _mbar = (uint32_t)(mbar_smem_addr); \
    uint32_t _parity = (uint32_t)(phase_parity); \
    uint32_t _done; \
    asm volatile( \
        "{\n\t" \
        ".reg .pred p;\n\t" \
        "mbarrier.try_wait.parity.acquire.cta.shared::cta.b64 p, [%1], %2;\n\t" \
        "selp.b32 %0, 1, 0, p;\n\t" \
        "}" \
        : "=r"(_done) : "r"(_mbar), "r"(_parity) : "memory"); \
    if (!_done) { \
        asm volatile( \
            "{\n\t" \
            ".reg .pred P1;\n\t" \
            "WAIT_LOOP_%=:\n\t" \
            "mbarrier.try_wait.parity.acquire.cta.shared::cta.b64 P1, [%0], %1, 0x989680;\n\t" \
            "@P1 bra.uni WAIT_DONE_%=;\n\t" \
            "bra.uni WAIT_LOOP_%=;\n\t" \
            "WAIT_DONE_%=:\n\t" \
            "}" \
            :: "r"(_mbar), "r"(_parity) : "memory"); \
    } \
} while(0)

#define TCGEN05_LD_32X32B_X32(r, tmem_addr) \
    asm volatile( \
        "tcgen05.ld.sync.aligned.32x32b.x32.b32 " \
        "{%0, %1, %2, %3, %4, %5, %6, %7, " \
        " %8, %9, %10, %11, %12, %13, %14, %15, " \
        " %16, %17, %18, %19, %20, %21, %22, %23, " \
        " %24, %25, %26, %27, %28, %29, %30, %31}, [%32];" \
        : "=r"((r)[0]),  "=r"((r)[1]),  "=r"((r)[2]),  "=r"((r)[3]), \
          "=r"((r)[4]),  "=r"((r)[5]),  "=r"((r)[6]),  "=r"((r)[7]), \
          "=r"((r)[8]),  "=r"((r)[9]),  "=r"((r)[10]), "=r"((r)[11]), \
          "=r"((r)[12]), "=r"((r)[13]), "=r"((r)[14]), "=r"((r)[15]), \
          "=r"((r)[16]), "=r"((r)[17]), "=r"((r)[18]), "=r"((r)[19]), \
          "=r"((r)[20]), "=r"((r)[21]), "=r"((r)[22]), "=r"((r)[23]), \
          "=r"((r)[24]), "=r"((r)[25]), "=r"((r)[26]), "=r"((r)[27]), \
          "=r"((r)[28]), "=r"((r)[29]), "=r"((r)[30]), "=r"((r)[31]) \
        : "r"(tmem_addr))

static constexpr uint64_t SMEM_DESC_BASE_SW128 =
    (uint64_t(2)  << 61)
    | (uint64_t(1) << 46)
    | (uint64_t(64) << 32)
    | (uint64_t(1) << 16);

#define MAKE_SMEM_DESC(base_addr) \
    (SMEM_DESC_BASE_SW128 | ((uint64_t)((base_addr) >> 4) & 0x3FFF))

// SS bf16 MMA, cta_group::1, fp32 accumulate
__device__ __forceinline__ void mma_f16_ss(uint32_t d, uint64_t a, uint64_t b,
                                           uint32_t idesc, uint32_t en)
{
    asm volatile(
        "{\n\t"
        ".reg .pred p;\n\t"
        "setp.ne.u32 p, %4, 0;\n\t"
        "tcgen05.mma.cta_group::1.kind::f16 [%0], %1, %2, %3, {%5, %5, %5, %5}, p;\n\t"
        "}"
        :: "r"(d), "l"(a), "l"(b), "r"(idesc), "r"(en), "r"(0u)
        : "memory");
}

// cp.async 16B global->smem (cg = L2-only path); src_bytes=0 zero-fills
__device__ __forceinline__ void cp_async16(uint32_t dst, const void* src, int src_bytes)
{
    asm volatile("cp.async.cg.shared.global [%0], [%1], 16, %2;"
                 :: "r"(dst), "l"(src), "r"(src_bytes) : "memory");
}

#define CP_ASYNC_COMMIT() asm volatile("cp.async.commit_group;" ::: "memory")
#define CP_ASYNC_WAIT(n)  asm volatile("cp.async.wait_group %0;" :: "n"(n) : "memory")

#endif  // HAS_TCGEN05

// idesc: F32 acc, BF16 x BF16, M=128, N=256
static constexpr uint32_t IDESC =
    (1u << 4) | (1u << 7) | (1u << 10) | ((HID / 8) << 17) | ((128 / 16) << 24);

// ---------------------------------------------------------------------------
// scratch buffers
// ---------------------------------------------------------------------------
__device__ float g_xin[(size_t)MAXN * INCH];
__device__ float g_agg[(size_t)MAXN * INCH];
__device__ __nv_bfloat16 g_a1[(size_t)MAXN * 256];   // (xin+agg) split [hi|lo]
__device__ __nv_bfloat16 g_a2[(size_t)MAXN * 512];   // L1 out split [hi|lo]
__device__ __nv_bfloat16 g_a3[(size_t)MAXN * 768];   // [h_hi|xin_hi|h_lo|xin_lo]
__device__ __nv_bfloat16 g_a4[(size_t)MAXN * 512];   // L3 out split [hi|lo]
__device__ __nv_bfloat16 g_wt1[(size_t)HID * 384];
__device__ __nv_bfloat16 g_wt2[(size_t)HID * 768];
__device__ __nv_bfloat16 g_wt3[(size_t)HID * 1152];
__device__ __nv_bfloat16 g_wt4[(size_t)HID * 768];

__device__ __forceinline__ void split_bf16(float v, __nv_bfloat16& h, __nv_bfloat16& l)
{
    h = __float2bfloat16(v);
    l = __float2bfloat16(v - __bfloat162float(h));
}

__device__ __forceinline__ float apply_act(float v, int ACT)
{
    if (ACT == 1)      v = fmaxf(v, 0.f);
    else if (ACT == 2) v = fmaxf(tanhf(v), 0.f);
    else if (ACT == 3) v = (v > 0.f) ? v : 0.2f * v;
    return v;
}

// ---------------------------------------------------------------------------
// K0: build x_in (fp32 for scatter) + write xin split into A3 cols, zero agg
// ---------------------------------------------------------------------------
__global__ void build_xin_kernel(const float* __restrict__ x,
                                 const float* __restrict__ t,
                                 float* __restrict__ xin,
                                 float* __restrict__ agg,
                                 __nv_bfloat16* __restrict__ a3,
                                 int M)
{
    int idx = blockIdx.x * blockDim.x + threadIdx.x;
    int total = M * INCH;
    if (idx >= total) return;
    int row = idx >> 7;
    int col = idx & 127;
    float v = (col < 127) ? x[(size_t)row * 127 + col] : t[row];
    xin[idx] = v;
    agg[idx] = 0.0f;
    __nv_bfloat16 h, l;
    split_bf16(v, h, l);
    a3[(size_t)row * 768 + 256 + col] = h;
    a3[(size_t)row * 768 + 640 + col] = l;
}

// ---------------------------------------------------------------------------
// K1: scatter add, one warp per edge, red.global.add.v4.f32
// ---------------------------------------------------------------------------
__device__ __forceinline__ void red_add_v4(float* addr, float4 v)
{
    asm volatile("red.global.add.v4.f32 [%0], {%1,%2,%3,%4};"
                 :: "l"(addr), "f"(v.x), "f"(v.y), "f"(v.z), "f"(v.w)
                 : "memory");
}

__global__ void scatter_kernel(const int* __restrict__ src,
                               const int* __restrict__ dst,
                               const float* __restrict__ xin,
                               float* __restrict__ agg,
                               int E)
{
    int warp = (blockIdx.x * blockDim.x + threadIdx.x) >> 5;
    int lane = threadIdx.x & 31;
    if (warp >= E) return;
    int s = src[warp];
    int d = dst[warp];
    const float4* ps = reinterpret_cast<const float4*>(xin + (size_t)s * INCH);
    float4 v = ps[lane];
    red_add_v4(agg + (size_t)d * INCH + lane * 4, v);
}

// ---------------------------------------------------------------------------
// K2: split (xin + agg) into compact bf16 a1 [M, 256] = [hi | lo]
// ---------------------------------------------------------------------------
__global__ void split1_kernel(const float* __restrict__ xin,
                              const float* __restrict__ agg,
                              __nv_bfloat16* __restrict__ a1,
                              int M)
{
    int idx = blockIdx.x * blockDim.x + threadIdx.x;
    int total = M * INCH;
    if (idx >= total) return;
    int row = idx >> 7;
    int col = idx & 127;
    float v = xin[idx] + agg[idx];
    __nv_bfloat16 h, l;
    split_bf16(v, h, l);
    a1[(size_t)row * 256 + col] = h;
    a1[(size_t)row * 256 + 128 + col] = l;
}

// ---------------------------------------------------------------------------
// K3: all weight preps in one kernel.
// Wt'[n][k'] (K-major, Ktot=3K): seg0 -> hi, seg1 -> lo, seg2 -> hi
// ---------------------------------------------------------------------------
__device__ __forceinline__ void prep_one(const float* __restrict__ W,
                                         __nv_bfloat16* __restrict__ Wt,
                                         int K, int idx)
{
    int Ktot = 3 * K;
    int n  = idx / Ktot;
    int kp = idx - n * Ktot;
    int seg = kp / K;
    int k   = kp - seg * K;
    float w = W[(size_t)k * HID + n];
    __nv_bfloat16 h, l;
    split_bf16(w, h, l);
    Wt[idx] = (seg == 1) ? l : h;
}

__global__ void prep_all_kernel(const float* __restrict__ W1,
                                const float* __restrict__ W2,
                                const float* __restrict__ P1,
                                const float* __restrict__ P2,
                                __nv_bfloat16* __restrict__ wt1,
                                __nv_bfloat16* __restrict__ wt2,
                                __nv_bfloat16* __restrict__ wt3,
                                __nv_bfloat16* __restrict__ wt4)
{
    const int s1 = HID * 384;
    const int s2 = s1 + HID * 768;
    const int s3 = s2 + HID * 1152;
    const int s4 = s3 + HID * 768;
    int idx = blockIdx.x * blockDim.x + threadIdx.x;
    if (idx < s1)       prep_one(W1, wt1, 128, idx);
    else if (idx < s2)  prep_one(W2, wt2, 256, idx - s1);
    else if (idx < s3)  prep_one(P1, wt3, 384, idx - s2);
    else if (idx < s4)  prep_one(P2, wt4, 256, idx - s3);
}

// ---------------------------------------------------------------------------
// tcgen05 GEMM with cp.async 2-stage pipeline:
//   C[128-tile, 256] = act(A' @ W'^T + bias)
//   A bf16 [M, strideA], hi cols [0,K), lo cols [K,2K);
//   chunk k0 reads A-col (k0 < K ? k0 : k0 - K)
//   Wt bf16 [256, Ktot] K-major ([hi|lo|hi])
//   SPLIT: write bf16 hi/lo activations; GEMV: fuse final 256->1 layer
// ---------------------------------------------------------------------------
#define SMEM_BYTES 99328
#define SA_OFF(s) (1024u + (uint32_t)(s) * 49152u)
#define SB_OFF(s) (SA_OFF(s) + 16384u)

template<int ACT, bool SPLIT, bool GEMV>
__global__ void __launch_bounds__(256)
tc_gemm(const __nv_bfloat16* __restrict__ A, int strideA, int K,
        const __nv_bfloat16* __restrict__ Wt, int Ktot,
        const float* __restrict__ bias,
        __nv_bfloat16* __restrict__ outHi, __nv_bfloat16* __restrict__ outLo,
        int strideO,
        float* __restrict__ outF, const float* __restrict__ P3,
        const float* __restrict__ pb3, int M)
{
#if HAS_TCGEN05
    extern __shared__ char smem[];
    const uint32_t smem_base = smem_to_u32(smem);
    const int tid = threadIdx.x;
    const int wid = tid >> 5;
    const int row0 = blockIdx.x * 128;
    const int nch = Ktot / 64;

    if (wid == 0) {
        TCGEN05_ALLOC(smem_base, 256);
    }
    if (tid == 0) {
        MBARRIER_INIT(smem_base + 8, 1);
        MBARRIER_INIT(smem_base + 16, 1);
        MBARRIER_INIT(smem_base + 24, 1);
    }
    __syncthreads();
    uint32_t tmem_base;
    asm volatile("ld.shared.b32 %0, [%1];" : "=r"(tmem_base) : "r"(smem_base));

    // per-thread load coordinates (fixed across chunks)
    const int ar = tid >> 1;                 // A row in tile (2 threads/row)
    const int au = (tid & 1) * 4;            // A 16B-seg base (4 segs per half-row... 8 segs/row, 4 per thread)
    const int arow = row0 + ar;
    const int aval = (arow < M) ? 16 : 0;
    const int bn = tid >> 1;                 // B rows 0..127 handled by pairs, 2 rows per thread via +128
    // A: 128 rows x 8 segs = 1024 segs, 256 thr -> 4 segs each (row=tid>>1, segs au..au+3)
    // B: 256 rows x 8 segs = 2048 segs, 256 thr -> 8 segs each (rows bn and bn+128, segs bu..bu+3)
    const int bu = (tid & 1) * 4;

    // chunk load: issue 12 cp.async ops for chunk c into stage s
    auto issue_chunk = [&](int c, int s) {
        const uint32_t sa = smem_base + SA_OFF(s);
        const uint32_t sb = smem_base + SB_OFF(s);
        const int k0 = c * 64;
        const int sc = (k0 < K) ? k0 : (k0 - K);
        const __nv_bfloat16* Asrc = A + (size_t)arow * strideA + sc + au * 8;
        #pragma unroll
        for (int i = 0; i < 4; i++) {
            int off = ar * 128 + (au + i) * 16;
            off ^= (off >> 3) & 0x70;
            cp_async16(sa + off, Asrc + i * 8, aval);
        }
        const __nv_bfloat16* B0 = Wt + (size_t)bn * Ktot + k0 + bu * 8;
        const __nv_bfloat16* B1 = Wt + (size_t)(bn + 128) * Ktot + k0 + bu * 8;
        #pragma unroll
        for (int i = 0; i < 4; i++) {
            int off0 = bn * 128 + (bu + i) * 16;
            off0 ^= (off0 >> 3) & 0x70;
            cp_async16(sb + off0, B0 + i * 8, 16);
            int off1 = (bn + 128) * 128 + (bu + i) * 16;
            off1 ^= (off1 >> 3) & 0x70;
            cp_async16(sb + off1, B1 + i * 8, 16);
        }
        CP_ASYNC_COMMIT();
    };

    // prologue: chunks 0 and 1 in flight
    issue_chunk(0, 0);
    if (nch > 1) issue_chunk(1, 1);

    int ph0 = 0, ph1 = 0;
    for (int c = 0; c < nch; c++) {
        const int s = c & 1;
        const uint32_t mb = smem_base + 8 + s * 8;
        if (c + 1 < nch) { CP_ASYNC_WAIT(1); } else { CP_ASYNC_WAIT(0); }
        __syncthreads();
        FENCE_PROXY_ASYNC_SHARED_CTA();
        if (wid == 0) {
            if (elect_one_pred()) {
                uint64_t ad = MAKE_SMEM_DESC(smem_base + SA_OFF(s));
                uint64_t bd = MAKE_SMEM_DESC(smem_base + SB_OFF(s));
                #pragma unroll
                for (int st = 0; st < 4; st++)
                    mma_f16_ss(tmem_base, ad + st * 2, bd + st * 2, IDESC,
                               (c > 0 || st > 0) ? 1u : 0u);
                TCGEN05_COMMIT(mb);
            }
        }
        if (c + 2 < nch) {
            // stage s must be released by MMA of chunk c before refill
            if (s == 0) { MBARRIER_WAIT_PARITY(mb, ph0); ph0 ^= 1; }
            else        { MBARRIER_WAIT_PARITY(mb, ph1); ph1 ^= 1; }
            issue_chunk(c + 2, s);
        }
    }
    if (wid == 0) {
        if (elect_one_pred()) TCGEN05_COMMIT(smem_base + 24);
    }

    // epilogue: warps 0-3 read D (128 x 256 fp32) from TMEM, 64 cols per batch
    if (wid < 4) {
        MBARRIER_WAIT_PARITY(smem_base + 24, 0);
        TCGEN05_FENCE_AFTER();
        const int lane = tid & 31;
        const int row = row0 + wid * 32 + lane;
        const bool valid = (row < M);
        float gsum = 0.0f;
        #pragma unroll 1
        for (int b = 0; b < 4; b++) {
            uint32_t regs[64];
            TCGEN05_LD_32X32B_X32(regs, tmem_base + b * 64);
            TCGEN05_LD_32X32B_X32(regs + 32, tmem_base + b * 64 + 32);
            TCGEN05_WAIT_LD();
            if (valid) {
                #pragma unroll
                for (int j = 0; j < 64; j += 2) {
                    int col = b * 64 + j;
                    float v0 = apply_act(__uint_as_float(regs[j])     + __ldg(bias + col), ACT);
                    float v1 = apply_act(__uint_as_float(regs[j + 1]) + __ldg(bias + col + 1), ACT);
                    if (GEMV) {
                        gsum += v0 * __ldg(P3 + col) + v1 * __ldg(P3 + col + 1);
                    }
                    if (SPLIT) {
                        __nv_bfloat16 h0, l0, h1, l1;
                        split_bf16(v0, h0, l0);
                        split_bf16(v1, h1, l1);
                        __nv_bfloat162 hv; hv.x = h0; hv.y = h1;
                        __nv_bfloat162 lv; lv.x = l0; lv.y = l1;
                        *reinterpret_cast<__nv_bfloat162*>(outHi + (size_t)row * strideO + col) = hv;
                        *reinterpret_cast<__nv_bfloat162*>(outLo + (size_t)row * strideO + col) = lv;
                    }
                }
            }
        }
        if (GEMV && valid) {
            outF[row] = 0.0f;                       // t_pred
            outF[(size_t)M + row] = gsum + __ldg(pb3);
        }
        TCGEN05_FENCE_BEFORE();
    }
    __syncthreads();
    if (wid == 0) {
        TCGEN05_RELINQUISH_ALLOC_PERMIT();
        TCGEN05_DEALLOC(tmem_base, 256);
    }
#else
    // ---- fallback (non arch-specific pass only): correct, slow SIMT path
    const int tid = threadIdx.x;
    const int row0 = blockIdx.x * 128;
    if (GEMV) {
        if (tid < 128) {
            int row = row0 + tid;
            if (row < M) {
                float gsum = 0.0f;
                for (int col = 0; col < HID; col++) {
                    const __nv_bfloat16* Wr = Wt + (size_t)col * Ktot;
                    float sum = 0.0f;
                    for (int kp = 0; kp < Ktot; kp++) {
                        int sc = (kp < K) ? kp : (kp - K);
                        float av = __bfloat162float(A[(size_t)row * strideA + sc]);
                        sum = fmaf(av, __bfloat162float(Wr[kp]), sum);
                    }
                    float v = apply_act(sum + bias[col], ACT);
                    gsum += v * P3[col];
                }
                outF[row] = 0.0f;
                outF[(size_t)M + row] = gsum + pb3[0];
            }
        }
    } else {
        for (int idx = tid; idx < 128 * HID; idx += 256) {
            int r = idx >> 8;
            int col = idx & 255;
            int row = row0 + r;
            if (row >= M) continue;
            const __nv_bfloat16* Wr = Wt + (size_t)col * Ktot;
            float sum = 0.0f;
            for (int kp = 0; kp < Ktot; kp++) {
                int sc = (kp < K) ? kp : (kp - K);
                float av = __bfloat162float(A[(size_t)row * strideA + sc]);
                sum = fmaf(av, __bfloat162float(Wr[kp]), sum);
            }
            float v = apply_act(sum + bias[col], ACT);
            if (SPLIT) {
                __nv_bfloat16 h, l;
                split_bf16(v, h, l);
                outHi[(size_t)row * strideO + col] = h;
                outLo[(size_t)row * strideO + col] = l;
            }
        }
    }
#endif
}

// ---------------------------------------------------------------------------
extern "C" void kernel_launch(void* const* d_in, const int* in_sizes, int n_in,
                              void* d_out, int out_size)
{
    const float* x   = (const float*)d_in[0];
    const float* t   = (const float*)d_in[1];
    const int*   ei  = (const int*)d_in[3];
    const float* W1  = (const float*)d_in[4];
    const float* b1  = (const float*)d_in[5];
    const float* W2  = (const float*)d_in[6];
    const float* b2  = (const float*)d_in[7];
    const float* P1  = (const float*)d_in[8];
    const float* pb1 = (const float*)d_in[9];
    const float* P2  = (const float*)d_in[10];
    const float* pb2 = (const float*)d_in[11];
    const float* P3  = (const float*)d_in[12];
    const float* pb3 = (const float*)d_in[13];
    float* out = (float*)d_out;

    const int M = in_sizes[1];
    const int E = in_sizes[3] / 2;

    float *xin, *agg;
    __nv_bfloat16 *a1, *a2, *a3, *a4, *wt1, *wt2, *wt3, *wt4;
    cudaGetSymbolAddress((void**)&xin, g_xin);
    cudaGetSymbolAddress((void**)&agg, g_agg);
    cudaGetSymbolAddress((void**)&a1,  g_a1);
    cudaGetSymbolAddress((void**)&a2,  g_a2);
    cudaGetSymbolAddress((void**)&a3,  g_a3);
    cudaGetSymbolAddress((void**)&a4,  g_a4);
    cudaGetSymbolAddress((void**)&wt1, g_wt1);
    cudaGetSymbolAddress((void**)&wt2, g_wt2);
    cudaGetSymbolAddress((void**)&wt3, g_wt3);
    cudaGetSymbolAddress((void**)&wt4, g_wt4);

    cudaFuncSetAttribute(tc_gemm<1, true,  false>,
                         cudaFuncAttributeMaxDynamicSharedMemorySize, SMEM_BYTES);
    cudaFuncSetAttribute(tc_gemm<2, true,  false>,
                         cudaFuncAttributeMaxDynamicSharedMemorySize, SMEM_BYTES);
    cudaFuncSetAttribute(tc_gemm<3, true,  false>,
                         cudaFuncAttributeMaxDynamicSharedMemorySize, SMEM_BYTES);
    cudaFuncSetAttribute(tc_gemm<3, false, true>,
                         cudaFuncAttributeMaxDynamicSharedMemorySize, SMEM_BYTES);

    // 1: build x_in, zero agg, write xin split into a3
    {
        int total = M * INCH;
        build_xin_kernel<<<(total + 255) / 256, 256>>>(x, t, xin, agg, a3, M);
    }
    // 2: scatter add
    {
        int blocks = (E + 7) / 8;
        scatter_kernel<<<blocks, 256>>>(ei, ei + E, xin, agg, E);
    }
    // 3: split (xin+agg) -> a1
    {
        int total = M * INCH;
        split1_kernel<<<(total + 255) / 256, 256>>>(xin, agg, a1, M);
    }
    // 4: weight prep (all four)
    {
        int total = HID * (384 + 768 + 1152 + 768);
        prep_all_kernel<<<(total + 255) / 256, 256>>>(W1, W2, P1, P2,
                                                      wt1, wt2, wt3, wt4);
    }

    const int tiles = (M + 127) / 128;
    // 5: L1 relu(a1 @ W1 + b1)                 -> a2
    tc_gemm<1, true,  false><<<tiles, 256, SMEM_BYTES>>>(
        a1, 256, 128, wt1, 384, b1,
        a2, a2 + 256, 512, nullptr, nullptr, nullptr, M);
    // 6: L2 relu(tanh(. @ W2 + b2))            -> a3 (h part)
    tc_gemm<2, true,  false><<<tiles, 256, SMEM_BYTES>>>(
        a2, 512, 256, wt2, 768, b2,
        a3, a3 + 384, 768, nullptr, nullptr, nullptr, M);
    // 7: L3 leaky(concat(h,xin) @ P1 + pb1)    -> a4
    tc_gemm<3, true,  false><<<tiles, 256, SMEM_BYTES>>>(
        a3, 768, 384, wt3, 1152, pb1,
        a4, a4 + 256, 512, nullptr, nullptr, nullptr, M);
    // 8: L4 leaky(. @ P2 + pb2) fused with P3 gemv + out
    tc_gemm<3, false, true><<<tiles, 256, SMEM_BYTES>>>(
        a4, 512, 256, wt4, 768, pb2,
        nullptr, nullptr, 0, out, P3, pb3, M);
}

// round 7
// speedup vs baseline: 2.6099x; 1.2135x over previous
#include <cuda_runtime.h>
#include <cuda.h>
#include <cuda_bf16.h>
#include <math.h>
#include <cstdint>

#define MAXN 50000
#define INCH 128
#define HID  256

// tcgen05 is only available in the arch-specific (sm_103a / sm_100a) pass.
#if defined(__CUDA_ARCH__) && (defined(__CUDA_ARCH_FEAT_SM103_ALL) || defined(__CUDA_ARCH_FEAT_SM100_ALL))
#define HAS_TCGEN05 1
#else
#define HAS_TCGEN05 0
#endif

// ---------------------------------------------------------------------------
// PTX helpers (guarded: only expanded in the sm_103a pass)
// ---------------------------------------------------------------------------
#if HAS_TCGEN05

__device__ __forceinline__ uint32_t smem_to_u32(const void* smem_ptr) {
    uint32_t addr;
    asm("{ .reg .u64 tmp; cvta.to.shared.u64 tmp, %1; cvt.u32.u64 %0, tmp; }"
        : "=r"(addr) : "l"(smem_ptr));
    return addr;
}

#define TCGEN05_ALLOC(smem_result_addr, nCols) \
    asm volatile( \
        "tcgen05.alloc.cta_group::1.sync.aligned.shared::cta.b32 [%0], %1;" \
        :: "r"((uint32_t)(smem_result_addr)), "r"((uint32_t)(nCols)) \
        : "memory")

#define TCGEN05_DEALLOC(tmem_addr, nCols) \
    asm volatile( \
        "tcgen05.dealloc.cta_group::1.sync.aligned.b32 %0, %1;" \
        :: "r"(tmem_addr), "r"((uint32_t)(nCols)))

#define TCGEN05_RELINQUISH_ALLOC_PERMIT() \
    asm volatile("tcgen05.relinquish_alloc_permit.cta_group::1.sync.aligned;")

#define TCGEN05_COMMIT(mbar_smem_addr) \
    asm volatile( \
        "tcgen05.commit.cta_group::1.mbarrier::arrive::one.shared::cluster.b64 [%0];" \
        :: "r"((uint32_t)(mbar_smem_addr)) \
        : "memory")

#define TCGEN05_WAIT_LD() \
    asm volatile("tcgen05.wait::ld.sync.aligned;" ::: "memory")

#define TCGEN05_FENCE_BEFORE() \
    asm volatile("tcgen05.fence::before_thread_sync;" ::: "memory")

#define TCGEN05_FENCE_AFTER() \
    asm volatile("tcgen05.fence::after_thread_sync;" ::: "memory")

#define FENCE_PROXY_ASYNC_SHARED_CTA() \
    asm volatile("fence.proxy.async.shared::cta;" ::: "memory")

#define MBARRIER_INIT(mbar_smem_addr, count) \
    asm volatile( \
        "mbarrier.init.shared.b64 [%0], %1;" \
        :: "r"((uint32_t)(mbar_smem_addr)), "r"((uint32_t)(count)) \
        : "memory")

#define MBARRIER_EXPECT_TX(mbar_smem_addr, tx_bytes) \
    asm volatile( \
        "mbarrier.arrive.expect_tx.shared.b64 _, [%0], %1;" \
        :: "r"((uint32_t)(mbar_smem_addr)), "r"((uint32_t)(tx_bytes)) \
        : "memory")

#define MBARRIER_WAIT_PARITY(mbar_smem_addr, phase_parity) do { \
    uint32_t _mbar = (uint32_t)(mbar_smem_addr); \
    uint32_t _parity = (uint32_t)(phase_parity); \
    uint32_t _done; \
    asm volatile( \
        "{\n\t" \
        ".reg .pred p;\n\t" \
        "mbarrier.try_wait.parity.acquire.cta.shared::cta.b64 p, [%1], %2;\n\t" \
        "selp.b32 %0, 1, 0, p;\n\t" \
        "}" \
        : "=r"(_done) : "r"(_mbar), "r"(_parity) : "memory"); \
    if (!_done) { \
        asm volatile( \
            "{\n\t" \
            ".reg .pred P1;\n\t" \
            "WAIT_LOOP_%=:\n\t" \
            "mbarrier.try_wait.parity.acquire.cta.shared::cta.b64 P1, [%0], %1, 0x989680;\n\t" \
            "@P1 bra.uni WAIT_DONE_%=;\n\t" \
            "bra.uni WAIT_LOOP_%=;\n\t" \
            "WAIT_DONE_%=:\n\t" \
            "}" \
            :: "r"(_mbar), "r"(_parity) : "memory"); \
    } \
} while(0)

#define TMA_LOAD_2D(smem_addr, map_ptr, cx, cy, mbar) \
    asm volatile( \
        "cp.async.bulk.tensor.2d.shared::cta.global.tile.mbarrier::complete_tx::bytes " \
        "[%0], [%1, {%2, %3}], [%4];" \
        :: "r"((uint32_t)(smem_addr)), "l"(map_ptr), "r"((int)(cx)), "r"((int)(cy)), \
           "r"((uint32_t)(mbar)) \
        : "memory")

#define TCGEN05_LD_32X32B_X32(r, tmem_addr) \
    asm volatile( \
        "tcgen05.ld.sync.aligned.32x32b.x32.b32 " \
        "{%0, %1, %2, %3, %4, %5, %6, %7, " \
        " %8, %9, %10, %11, %12, %13, %14, %15, " \
        " %16, %17, %18, %19, %20, %21, %22, %23, " \
        " %24, %25, %26, %27, %28, %29, %30, %31}, [%32];" \
        : "=r"((r)[0]),  "=r"((r)[1]),  "=r"((r)[2]),  "=r"((r)[3]), \
          "=r"((r)[4]),  "=r"((r)[5]),  "=r"((r)[6]),  "=r"((r)[7]), \
          "=r"((r)[8]),  "=r"((r)[9]),  "=r"((r)[10]), "=r"((r)[11]), \
          "=r"((r)[12]), "=r"((r)[13]), "=r"((r)[14]), "=r"((r)[15]), \
          "=r"((r)[16]), "=r"((r)[17]), "=r"((r)[18]), "=r"((r)[19]), \
          "=r"((r)[20]), "=r"((r)[21]), "=r"((r)[22]), "=r"((r)[23]), \
          "=r"((r)[24]), "=r"((r)[25]), "=r"((r)[26]), "=r"((r)[27]), \
          "=r"((r)[28]), "=r"((r)[29]), "=r"((r)[30]), "=r"((r)[31]) \
        : "r"(tmem_addr))

static constexpr uint64_t SMEM_DESC_BASE_SW128 =
    (uint64_t(2)  << 61)
    | (uint64_t(1) << 46)
    | (uint64_t(64) << 32)
    | (uint64_t(1) << 16);

#define MAKE_SMEM_DESC(base_addr) \
    (SMEM_DESC_BASE_SW128 | ((uint64_t)((base_addr) >> 4) & 0x3FFF))

// SS bf16 MMA, cta_group::1, fp32 accumulate
__device__ __forceinline__ void mma_f16_ss(uint32_t d, uint64_t a, uint64_t b,
                                           uint32_t idesc, uint32_t en)
{
    asm volatile(
        "{\n\t"
        ".reg .pred p;\n\t"
        "setp.ne.u32 p, %4, 0;\n\t"
        "tcgen05.mma.cta_group::1.kind::f16 [%0], %1, %2, %3, {%5, %5, %5, %5}, p;\n\t"
        "}"
        :: "r"(d), "l"(a), "l"(b), "r"(idesc), "r"(en), "r"(0u)
        : "memory");
}

#endif  // HAS_TCGEN05

// idesc: F32 acc, BF16 x BF16, M=128, N=256
static constexpr uint32_t IDESC =
    (1u << 4) | (1u << 7) | (1u << 10) | ((HID / 8) << 17) | ((128 / 16) << 24);

// ---------------------------------------------------------------------------
// scratch buffers
// ---------------------------------------------------------------------------
__device__ float g_xin[(size_t)MAXN * INCH];
__device__ float g_agg[(size_t)MAXN * INCH];
__device__ __nv_bfloat16 g_a1[(size_t)MAXN * 256];   // (xin+agg) split [hi|lo]
__device__ __nv_bfloat16 g_a2[(size_t)MAXN * 512];   // L1 out split [hi|lo]
__device__ __nv_bfloat16 g_a3[(size_t)MAXN * 768];   // [h_hi|xin_hi|h_lo|xin_lo]
__device__ __nv_bfloat16 g_a4[(size_t)MAXN * 512];   // L3 out split [hi|lo]
__device__ __nv_bfloat16 g_wt1[(size_t)HID * 384];
__device__ __nv_bfloat16 g_wt2[(size_t)HID * 768];
__device__ __nv_bfloat16 g_wt3[(size_t)HID * 1152];
__device__ __nv_bfloat16 g_wt4[(size_t)HID * 768];

__device__ __forceinline__ void split_bf16(float v, __nv_bfloat16& h, __nv_bfloat16& l)
{
    h = __float2bfloat16(v);
    l = __float2bfloat16(v - __bfloat162float(h));
}

__device__ __forceinline__ float apply_act(float v, int ACT)
{
    if (ACT == 1)      v = fmaxf(v, 0.f);
    else if (ACT == 2) v = fmaxf(tanhf(v), 0.f);
    else if (ACT == 3) v = (v > 0.f) ? v : 0.2f * v;
    return v;
}

// ---------------------------------------------------------------------------
// K0: build x_in (fp32 for scatter) + write xin split into A3 cols, zero agg
// ---------------------------------------------------------------------------
__global__ void build_xin_kernel(const float* __restrict__ x,
                                 const float* __restrict__ t,
                                 float* __restrict__ xin,
                                 float* __restrict__ agg,
                                 __nv_bfloat16* __restrict__ a3,
                                 int M)
{
    int idx = blockIdx.x * blockDim.x + threadIdx.x;
    int total = M * INCH;
    if (idx >= total) return;
    int row = idx >> 7;
    int col = idx & 127;
    float v = (col < 127) ? x[(size_t)row * 127 + col] : t[row];
    xin[idx] = v;
    agg[idx] = 0.0f;
    __nv_bfloat16 h, l;
    split_bf16(v, h, l);
    a3[(size_t)row * 768 + 256 + col] = h;
    a3[(size_t)row * 768 + 640 + col] = l;
}

// ---------------------------------------------------------------------------
// K1: scatter add, one warp per edge, red.global.add.v4.f32
// ---------------------------------------------------------------------------
__device__ __forceinline__ void red_add_v4(float* addr, float4 v)
{
    asm volatile("red.global.add.v4.f32 [%0], {%1,%2,%3,%4};"
                 :: "l"(addr), "f"(v.x), "f"(v.y), "f"(v.z), "f"(v.w)
                 : "memory");
}

__global__ void scatter_kernel(const int* __restrict__ src,
                               const int* __restrict__ dst,
                               const float* __restrict__ xin,
                               float* __restrict__ agg,
                               int E)
{
    int warp = (blockIdx.x * blockDim.x + threadIdx.x) >> 5;
    int lane = threadIdx.x & 31;
    if (warp >= E) return;
    int s = src[warp];
    int d = dst[warp];
    const float4* ps = reinterpret_cast<const float4*>(xin + (size_t)s * INCH);
    float4 v = ps[lane];
    red_add_v4(agg + (size_t)d * INCH + lane * 4, v);
}

// ---------------------------------------------------------------------------
// K2 (aux): split1 (xin+agg -> a1) AND all weight preps, fused in one launch
// ---------------------------------------------------------------------------
__device__ __forceinline__ void prep_one(const float* __restrict__ W,
                                         __nv_bfloat16* __restrict__ Wt,
                                         int K, int idx)
{
    int Ktot = 3 * K;
    int n  = idx / Ktot;
    int kp = idx - n * Ktot;
    int seg = kp / K;
    int k   = kp - seg * K;
    float w = W[(size_t)k * HID + n];
    __nv_bfloat16 h, l;
    split_bf16(w, h, l);
    Wt[idx] = (seg == 1) ? l : h;
}

__global__ void aux_kernel(const float* __restrict__ xin,
                           const float* __restrict__ agg,
                           __nv_bfloat16* __restrict__ a1,
                           const float* __restrict__ W1,
                           const float* __restrict__ W2,
                           const float* __restrict__ P1,
                           const float* __restrict__ P2,
                           __nv_bfloat16* __restrict__ wt1,
                           __nv_bfloat16* __restrict__ wt2,
                           __nv_bfloat16* __restrict__ wt3,
                           __nv_bfloat16* __restrict__ wt4,
                           int M)
{
    int idx = blockIdx.x * blockDim.x + threadIdx.x;
    int totalS = M * INCH;
    if (idx < totalS) {
        int row = idx >> 7;
        int col = idx & 127;
        float v = xin[idx] + agg[idx];
        __nv_bfloat16 h, l;
        split_bf16(v, h, l);
        a1[(size_t)row * 256 + col] = h;
        a1[(size_t)row * 256 + 128 + col] = l;
        return;
    }
    int w = idx - totalS;
    const int s1 = HID * 384;
    const int s2 = s1 + HID * 768;
    const int s3 = s2 + HID * 1152;
    const int s4 = s3 + HID * 768;
    if (w < s1)       prep_one(W1, wt1, 128, w);
    else if (w < s2)  prep_one(W2, wt2, 256, w - s1);
    else if (w < s3)  prep_one(P1, wt3, 384, w - s2);
    else if (w < s4)  prep_one(P2, wt4, 256, w - s3);
}

// ---------------------------------------------------------------------------
// tcgen05 GEMM, TMA + mbarrier 4-stage pipeline, single driver thread.
//   C[128-tile, 256] = act(A' @ W'^T + bias)
//   A bf16 [M, strideA] via mapA (box 64x128), hi cols [0,K), lo cols [K,2K);
//   chunk k0 reads A-col (k0 < K ? k0 : k0 - K)
//   Wt bf16 [256, Ktot] via mapB (box 64x256)
//   SPLIT: write bf16 hi/lo activations; GEMV: fuse final 256->1 layer
// ---------------------------------------------------------------------------
#define NSTAGE 4
#define STAGE_BYTES 49152u
#define SMEM_BYTES (1024u + NSTAGE * STAGE_BYTES)
#define SA_OFF(s) (1024u + (uint32_t)(s) * STAGE_BYTES)
#define SB_OFF(s) (SA_OFF(s) + 16384u)
// mbarrier smem offsets
#define MB_FULL(s)  (8u + 8u * (uint32_t)(s))
#define MB_EMPTY(s) (40u + 8u * (uint32_t)(s))
#define MB_DONE     72u

template<int ACT, bool SPLIT, bool GEMV>
__global__ void __launch_bounds__(128)
tc_gemm(const __grid_constant__ CUtensorMap mapA,
        const __grid_constant__ CUtensorMap mapB,
        const __nv_bfloat16* __restrict__ A, int strideA, int K,
        const __nv_bfloat16* __restrict__ Wt, int Ktot,
        const float* __restrict__ bias,
        __nv_bfloat16* __restrict__ outHi, __nv_bfloat16* __restrict__ outLo,
        int strideO,
        float* __restrict__ outF, const float* __restrict__ P3,
        const float* __restrict__ pb3, int M)
{
#if HAS_TCGEN05
    extern __shared__ char smem[];
    const uint32_t smem_base = smem_to_u32(smem);
    const int tid = threadIdx.x;
    const int wid = tid >> 5;
    const int row0 = blockIdx.x * 128;
    const int nch = Ktot / 64;

    if (wid == 0) {
        TCGEN05_ALLOC(smem_base, 256);
    }
    if (tid == 0) {
        #pragma unroll
        for (int s = 0; s < NSTAGE; s++) {
            MBARRIER_INIT(smem_base + MB_FULL(s), 1);
            MBARRIER_INIT(smem_base + MB_EMPTY(s), 1);
        }
        MBARRIER_INIT(smem_base + MB_DONE, 1);
        FENCE_PROXY_ASYNC_SHARED_CTA();
    }
    __syncthreads();
    uint32_t tmem_base;
    asm volatile("ld.shared.b32 %0, [%1];" : "=r"(tmem_base) : "r"(smem_base));

    if (tid == 0) {
        const CUtensorMap* mA = &mapA;
        const CUtensorMap* mB = &mapB;
        // prologue: fill up to NSTAGE stages
        const int pre = (nch < NSTAGE) ? nch : NSTAGE;
        for (int c = 0; c < pre; c++) {
            const int s = c;
            const int k0 = c * 64;
            const int sc = (k0 < K) ? k0 : (k0 - K);
            MBARRIER_EXPECT_TX(smem_base + MB_FULL(s), STAGE_BYTES);
            TMA_LOAD_2D(smem_base + SA_OFF(s), mA, sc, row0, smem_base + MB_FULL(s));
            TMA_LOAD_2D(smem_base + SB_OFF(s), mB, k0, 0,    smem_base + MB_FULL(s));
        }
        for (int c = 0; c < nch; c++) {
            const int s = c & (NSTAGE - 1);
            const uint32_t par = (uint32_t)(c >> 2) & 1u;
            MBARRIER_WAIT_PARITY(smem_base + MB_FULL(s), par);
            const uint64_t ad = MAKE_SMEM_DESC(smem_base + SA_OFF(s));
            const uint64_t bd = MAKE_SMEM_DESC(smem_base + SB_OFF(s));
            #pragma unroll
            for (int st = 0; st < 4; st++)
                mma_f16_ss(tmem_base, ad + st * 2, bd + st * 2, IDESC,
                           (c > 0 || st > 0) ? 1u : 0u);
            TCGEN05_COMMIT(smem_base + MB_EMPTY(s));
            const int n = c + NSTAGE;
            if (n < nch) {
                // stage reuse: wait MMA(c) completion, then refill with chunk n
                MBARRIER_WAIT_PARITY(smem_base + MB_EMPTY(s), par);
                const int k0 = n * 64;
                const int sc = (k0 < K) ? k0 : (k0 - K);
                MBARRIER_EXPECT_TX(smem_base + MB_FULL(s), STAGE_BYTES);
                TMA_LOAD_2D(smem_base + SA_OFF(s), mA, sc, row0, smem_base + MB_FULL(s));
                TMA_LOAD_2D(smem_base + SB_OFF(s), mB, k0, 0,    smem_base + MB_FULL(s));
            }
        }
        TCGEN05_COMMIT(smem_base + MB_DONE);
    }

    // epilogue: all 4 warps read D (128 x 256 fp32) from TMEM
    MBARRIER_WAIT_PARITY(smem_base + MB_DONE, 0);
    TCGEN05_FENCE_AFTER();
    {
        const int lane = tid & 31;
        const int row = row0 + wid * 32 + lane;
        const bool valid = (row < M);
        float gsum = 0.0f;
        #pragma unroll 1
        for (int b = 0; b < 4; b++) {
            uint32_t regs[64];
            TCGEN05_LD_32X32B_X32(regs, tmem_base + b * 64);
            TCGEN05_LD_32X32B_X32(regs + 32, tmem_base + b * 64 + 32);
            TCGEN05_WAIT_LD();
            if (valid) {
                #pragma unroll
                for (int j = 0; j < 64; j += 2) {
                    int col = b * 64 + j;
                    float v0 = apply_act(__uint_as_float(regs[j])     + __ldg(bias + col), ACT);
                    float v1 = apply_act(__uint_as_float(regs[j + 1]) + __ldg(bias + col + 1), ACT);
                    if (GEMV) {
                        gsum += v0 * __ldg(P3 + col) + v1 * __ldg(P3 + col + 1);
                    }
                    if (SPLIT) {
                        __nv_bfloat16 h0, l0, h1, l1;
                        split_bf16(v0, h0, l0);
                        split_bf16(v1, h1, l1);
                        __nv_bfloat162 hv; hv.x = h0; hv.y = h1;
                        __nv_bfloat162 lv; lv.x = l0; lv.y = l1;
                        *reinterpret_cast<__nv_bfloat162*>(outHi + (size_t)row * strideO + col) = hv;
                        *reinterpret_cast<__nv_bfloat162*>(outLo + (size_t)row * strideO + col) = lv;
                    }
                }
            }
        }
        if (GEMV && valid) {
            outF[row] = 0.0f;                       // t_pred
            outF[(size_t)M + row] = gsum + __ldg(pb3);
        }
        TCGEN05_FENCE_BEFORE();
    }
    __syncthreads();
    if (wid == 0) {
        TCGEN05_RELINQUISH_ALLOC_PERMIT();
        TCGEN05_DEALLOC(tmem_base, 256);
    }
#else
    // ---- fallback (non arch-specific pass only): correct, slow SIMT path
    const int tid = threadIdx.x;
    const int row0 = blockIdx.x * 128;
    if (GEMV) {
        if (tid < 128) {
            int row = row0 + tid;
            if (row < M) {
                float gsum = 0.0f;
                for (int col = 0; col < HID; col++) {
                    const __nv_bfloat16* Wr = Wt + (size_t)col * Ktot;
                    float sum = 0.0f;
                    for (int kp = 0; kp < Ktot; kp++) {
                        int sc = (kp < K) ? kp : (kp - K);
                        float av = __bfloat162float(A[(size_t)row * strideA + sc]);
                        sum = fmaf(av, __bfloat162float(Wr[kp]), sum);
                    }
                    float v = apply_act(sum + bias[col], ACT);
                    gsum += v * P3[col];
                }
                outF[row] = 0.0f;
                outF[(size_t)M + row] = gsum + pb3[0];
            }
        }
    } else {
        for (int idx = tid; idx < 128 * HID; idx += 128) {
            int r = idx >> 8;
            int col = idx & 255;
            int row = row0 + r;
            if (row >= M) continue;
            const __nv_bfloat16* Wr = Wt + (size_t)col * Ktot;
            float sum = 0.0f;
            for (int kp = 0; kp < Ktot; kp++) {
                int sc = (kp < K) ? kp : (kp - K);
                float av = __bfloat162float(A[(size_t)row * strideA + sc]);
                sum = fmaf(av, __bfloat162float(Wr[kp]), sum);
            }
            float v = apply_act(sum + bias[col], ACT);
            if (SPLIT) {
                __nv_bfloat16 h, l;
                split_bf16(v, h, l);
                outHi[(size_t)row * strideO + col] = h;
                outLo[(size_t)row * strideO + col] = l;
            }
        }
    }
#endif
}

// ---------------------------------------------------------------------------
// host: tensormap encoding via runtime-queried driver entry point (no -lcuda)
// ---------------------------------------------------------------------------
typedef CUresult (*EncodeTiledFn)(
    CUtensorMap*, CUtensorMapDataType, cuuint32_t, void*,
    const cuuint64_t*, const cuuint64_t*, const cuuint32_t*, const cuuint32_t*,
    CUtensorMapInterleave, CUtensorMapSwizzle, CUtensorMapL2promotion,
    CUtensorMapFloatOOBfill);

static EncodeTiledFn get_encoder()
{
    void* fn = nullptr;
    cudaDriverEntryPointQueryResult qr;
    cudaGetDriverEntryPointByVersion("cuTensorMapEncodeTiled", &fn, 12000,
                                     cudaEnableDefault, &qr);
    return (EncodeTiledFn)fn;
}

static void make_map(EncodeTiledFn enc, CUtensorMap* m, void* base,
                     uint64_t inner, uint64_t outer, uint32_t box0, uint32_t box1)
{
    cuuint64_t dims[2]    = {(cuuint64_t)inner, (cuuint64_t)outer};
    cuuint64_t strides[1] = {(cuuint64_t)(inner * 2)};
    cuuint32_t box[2]     = {(cuuint32_t)box0, (cuuint32_t)box1};
    cuuint32_t es[2]      = {1, 1};
    enc(m, CU_TENSOR_MAP_DATA_TYPE_BFLOAT16, 2, base, dims, strides, box, es,
        CU_TENSOR_MAP_INTERLEAVE_NONE, CU_TENSOR_MAP_SWIZZLE_128B,
        CU_TENSOR_MAP_L2_PROMOTION_L2_128B, CU_TENSOR_MAP_FLOAT_OOB_FILL_NONE);
}

// ---------------------------------------------------------------------------
extern "C" void kernel_launch(void* const* d_in, const int* in_sizes, int n_in,
                              void* d_out, int out_size)
{
    const float* x   = (const float*)d_in[0];
    const float* t   = (const float*)d_in[1];
    const int*   ei  = (const int*)d_in[3];
    const float* W1  = (const float*)d_in[4];
    const float* b1  = (const float*)d_in[5];
    const float* W2  = (const float*)d_in[6];
    const float* b2  = (const float*)d_in[7];
    const float* P1  = (const float*)d_in[8];
    const float* pb1 = (const float*)d_in[9];
    const float* P2  = (const float*)d_in[10];
    const float* pb2 = (const float*)d_in[11];
    const float* P3  = (const float*)d_in[12];
    const float* pb3 = (const float*)d_in[13];
    float* out = (float*)d_out;

    const int M = in_sizes[1];
    const int E = in_sizes[3] / 2;

    float *xin, *agg;
    __nv_bfloat16 *a1, *a2, *a3, *a4, *wt1, *wt2, *wt3, *wt4;
    cudaGetSymbolAddress((void**)&xin, g_xin);
    cudaGetSymbolAddress((void**)&agg, g_agg);
    cudaGetSymbolAddress((void**)&a1,  g_a1);
    cudaGetSymbolAddress((void**)&a2,  g_a2);
    cudaGetSymbolAddress((void**)&a3,  g_a3);
    cudaGetSymbolAddress((void**)&a4,  g_a4);
    cudaGetSymbolAddress((void**)&wt1, g_wt1);
    cudaGetSymbolAddress((void**)&wt2, g_wt2);
    cudaGetSymbolAddress((void**)&wt3, g_wt3);
    cudaGetSymbolAddress((void**)&wt4, g_wt4);

    // tensormaps (host-side, cheap; only runs during capture)
    EncodeTiledFn enc = get_encoder();
    CUtensorMap mA1, mA2, mA3, mA4, mB1, mB2, mB3, mB4;
    make_map(enc, &mA1, a1, 256, (uint64_t)M, 64, 128);
    make_map(enc, &mA2, a2, 512, (uint64_t)M, 64, 128);
    make_map(enc, &mA3, a3, 768, (uint64_t)M, 64, 128);
    make_map(enc, &mA4, a4, 512, (uint64_t)M, 64, 128);
    make_map(enc, &mB1, wt1, 384,  256, 64, 256);
    make_map(enc, &mB2, wt2, 768,  256, 64, 256);
    make_map(enc, &mB3, wt3, 1152, 256, 64, 256);
    make_map(enc, &mB4, wt4, 768,  256, 64, 256);

    cudaFuncSetAttribute(tc_gemm<1, true,  false>,
                         cudaFuncAttributeMaxDynamicSharedMemorySize, SMEM_BYTES);
    cudaFuncSetAttribute(tc_gemm<2, true,  false>,
                         cudaFuncAttributeMaxDynamicSharedMemorySize, SMEM_BYTES);
    cudaFuncSetAttribute(tc_gemm<3, true,  false>,
                         cudaFuncAttributeMaxDynamicSharedMemorySize, SMEM_BYTES);
    cudaFuncSetAttribute(tc_gemm<3, false, true>,
                         cudaFuncAttributeMaxDynamicSharedMemorySize, SMEM_BYTES);

    // 1: build x_in, zero agg, write xin split into a3
    {
        int total = M * INCH;
        build_xin_kernel<<<(total + 255) / 256, 256>>>(x, t, xin, agg, a3, M);
    }
    // 2: scatter add
    {
        int blocks = (E + 7) / 8;
        scatter_kernel<<<blocks, 256>>>(ei, ei + E, xin, agg, E);
    }
    // 3: aux (split1 + all weight preps)
    {
        int total = M * INCH + HID * (384 + 768 + 1152 + 768);
        aux_kernel<<<(total + 255) / 256, 256>>>(xin, agg, a1,
                                                 W1, W2, P1, P2,
                                                 wt1, wt2, wt3, wt4, M);
    }

    const int tiles = (M + 127) / 128;
    // 4: L1 relu(a1 @ W1 + b1)                 -> a2     (profiled by ncu)
    tc_gemm<1, true,  false><<<tiles, 128, SMEM_BYTES>>>(
        mA1, mB1, a1, 256, 128, wt1, 384, b1,
        a2, a2 + 256, 512, nullptr, nullptr, nullptr, M);
    // 5: L2 relu(tanh(. @ W2 + b2))            -> a3 (h part)
    tc_gemm<2, true,  false><<<tiles, 128, SMEM_BYTES>>>(
        mA2, mB2, a2, 512, 256, wt2, 768, b2,
        a3, a3 + 384, 768, nullptr, nullptr, nullptr, M);
    // 6: L3 leaky(concat(h,xin) @ P1 + pb1)    -> a4
    tc_gemm<3, true,  false><<<tiles, 128, SMEM_BYTES>>>(
        mA3, mB3, a3, 768, 384, wt3, 1152, pb1,
        a4, a4 + 256, 512, nullptr, nullptr, nullptr, M);
    // 7: L4 leaky(. @ P2 + pb2) fused with P3 gemv + out
    tc_gemm<3, false, true><<<tiles, 128, SMEM_BYTES>>>(
        mA4, mB4, a4, 512, 256, wt4, 768, pb2,
        nullptr, nullptr, 0, out, P3, pb3, M);
}